// round 1
// baseline (speedup 1.0000x reference)
#include <cuda_runtime.h>

#define L_SEQ 2048
#define EMB   512
#define NHEAD 8
#define HDIM  64
#define NTYPE 10

// Scratch (allocation-free rule: device globals)
__device__ float g_q[L_SEQ * EMB];
__device__ float g_k[L_SEQ * EMB];
__device__ float g_v[L_SEQ * EMB];
__device__ float g_ts[NHEAD * L_SEQ * 16];   // type scores, padded 10->16
__device__ float g_ctx[L_SEQ * EMB];

// ---------------------------------------------------------------------------
// C[M,N] = scale * (A[M,K] @ B[N,K]^T + bias[N])
// 64x64 tile, BK=16, 256 threads, 4x4 microkernel
// ---------------------------------------------------------------------------
__global__ __launch_bounds__(256) void gemm_abT(
    const float* __restrict__ A, const float* __restrict__ B,
    const float* __restrict__ bias, float* __restrict__ C,
    int M, int N, int K, float scale)
{
    __shared__ float As[16][68];
    __shared__ float Bs[16][68];
    int tid = threadIdx.x;
    int tx = tid & 15, ty = tid >> 4;
    int m0 = blockIdx.x * 64, n0 = blockIdx.y * 64;
    int lr = tid >> 2;           // 0..63 row within tile
    int lk = (tid & 3) << 2;     // k offset 0,4,8,12

    float acc[4][4] = {};
    const float* Ap = A + (m0 + lr) * K + lk;
    const float* Bp = B + (n0 + lr) * K + lk;

    for (int k0 = 0; k0 < K; k0 += 16) {
        float4 a4 = *(const float4*)(Ap + k0);
        float4 b4 = *(const float4*)(Bp + k0);
        As[lk + 0][lr] = a4.x; As[lk + 1][lr] = a4.y;
        As[lk + 2][lr] = a4.z; As[lk + 3][lr] = a4.w;
        Bs[lk + 0][lr] = b4.x; Bs[lk + 1][lr] = b4.y;
        Bs[lk + 2][lr] = b4.z; Bs[lk + 3][lr] = b4.w;
        __syncthreads();
        #pragma unroll
        for (int kk = 0; kk < 16; kk++) {
            float a[4], b[4];
            #pragma unroll
            for (int r = 0; r < 4; r++) a[r] = As[kk][ty * 4 + r];
            #pragma unroll
            for (int c = 0; c < 4; c++) b[c] = Bs[kk][tx * 4 + c];
            #pragma unroll
            for (int r = 0; r < 4; r++)
                #pragma unroll
                for (int c = 0; c < 4; c++)
                    acc[r][c] = fmaf(a[r], b[c], acc[r][c]);
        }
        __syncthreads();
    }
    #pragma unroll
    for (int r = 0; r < 4; r++) {
        int row = m0 + ty * 4 + r;
        #pragma unroll
        for (int c = 0; c < 4; c++) {
            int col = n0 + tx * 4 + c;
            C[row * N + col] = scale * (acc[r][c] + bias[col]);
        }
    }
}

// ---------------------------------------------------------------------------
// type_scores[h,i,t] = sum_d q[i, h*64+d] * edge_embs[t,d]   (q already scaled)
// one thread per (h,i)
// ---------------------------------------------------------------------------
__global__ __launch_bounds__(256) void type_scores_kernel(
    const float* __restrict__ edge_embs)
{
    __shared__ float emb[NTYPE * HDIM];
    int tid = threadIdx.x;
    for (int i = tid; i < NTYPE * HDIM; i += 256) emb[i] = edge_embs[i];
    __syncthreads();

    int gid = blockIdx.x * 256 + tid;      // over NHEAD * L_SEQ
    int h = gid >> 11;
    int i = gid & (L_SEQ - 1);
    const float* qrow = g_q + i * EMB + h * HDIM;
    float s[NTYPE] = {};
    for (int d = 0; d < HDIM; d++) {
        float qv = qrow[d];
        #pragma unroll
        for (int t = 0; t < NTYPE; t++) s[t] = fmaf(qv, emb[t * HDIM + d], s[t]);
    }
    float* dst = g_ts + gid * 16;
    #pragma unroll
    for (int t = 0; t < NTYPE; t++) dst[t] = s[t];
}

// ---------------------------------------------------------------------------
// Fused attention with edge-type bias. Block = (query tile of 64, head).
// Flash-style online softmax over 32 key tiles of 64.
// ---------------------------------------------------------------------------
__global__ __launch_bounds__(256) void attn_kernel(const int* __restrict__ edge_id)
{
    extern __shared__ float sm[];
    float* Qs = sm;                    // [64][68] row-major (row*68 + d)
    float* Ks = Qs + 64 * 68;          // transposed: [d][j] (d*68 + j)
    float* Vs = Ks + 64 * 68;          // [j][d]
    float* Ps = Vs + 64 * 68;          // [row][j]
    float* Ts = Ps + 64 * 68;          // [row][16] type-score LUT

    int h  = blockIdx.y;
    int i0 = blockIdx.x * 64;
    int tid = threadIdx.x;
    int tx = tid & 15, ty = tid >> 4;
    int lr = tid >> 2;                 // 0..63
    int lc = (tid & 3) << 4;           // 0,16,32,48

    // Load Q tile (row-major, conflict-safe reads later via 68 pad)
    #pragma unroll
    for (int rep = 0; rep < 4; rep++) {
        int d = lc + rep * 4;
        float4 v4 = *(const float4*)(g_q + (i0 + lr) * EMB + h * HDIM + d);
        *(float4*)(Qs + lr * 68 + d) = v4;
    }
    // Load type-score LUT for the 64 query rows
    {
        int t4 = (tid & 3) << 2;
        float4 v4 = *(const float4*)(g_ts + (h * L_SEQ + i0 + lr) * 16 + t4);
        *(float4*)(Ts + lr * 16 + t4) = v4;
    }

    float o[4][4] = {};
    float mrow[4], lrow[4];
    #pragma unroll
    for (int r = 0; r < 4; r++) { mrow[r] = -1e30f; lrow[r] = 0.f; }

    for (int jt = 0; jt < L_SEQ / 64; jt++) {
        int j0 = jt * 64;
        __syncthreads();   // prev iteration done reading Vs/Ps
        // Load K (transposed) and V (row-major) tiles
        #pragma unroll
        for (int rep = 0; rep < 4; rep++) {
            int d = lc + rep * 4;
            float4 kv = *(const float4*)(g_k + (j0 + lr) * EMB + h * HDIM + d);
            Ks[(d + 0) * 68 + lr] = kv.x;
            Ks[(d + 1) * 68 + lr] = kv.y;
            Ks[(d + 2) * 68 + lr] = kv.z;
            Ks[(d + 3) * 68 + lr] = kv.w;
            float4 vv = *(const float4*)(g_v + (j0 + lr) * EMB + h * HDIM + d);
            *(float4*)(Vs + lr * 68 + d) = vv;
        }
        __syncthreads();

        // S = Q @ K^T  (4x4 per thread)
        float s[4][4] = {};
        #pragma unroll 8
        for (int d = 0; d < 64; d++) {
            float a[4], b[4];
            #pragma unroll
            for (int r = 0; r < 4; r++) a[r] = Qs[(ty * 4 + r) * 68 + d];
            #pragma unroll
            for (int c = 0; c < 4; c++) b[c] = Ks[d * 68 + tx * 4 + c];
            #pragma unroll
            for (int r = 0; r < 4; r++)
                #pragma unroll
                for (int c = 0; c < 4; c++)
                    s[r][c] = fmaf(a[r], b[c], s[r][c]);
        }

        // edge-type bias via int4 gather + LUT
        #pragma unroll
        for (int r = 0; r < 4; r++) {
            int4 e = *(const int4*)(edge_id + (i0 + ty * 4 + r) * L_SEQ + j0 + tx * 4);
            const float* ts = Ts + (ty * 4 + r) * 16;
            s[r][0] += ts[e.x]; s[r][1] += ts[e.y];
            s[r][2] += ts[e.z]; s[r][3] += ts[e.w];
        }

        // online softmax (reduce across the 16 tx lanes sharing each row)
        #pragma unroll
        for (int r = 0; r < 4; r++) {
            float mx = fmaxf(fmaxf(s[r][0], s[r][1]), fmaxf(s[r][2], s[r][3]));
            #pragma unroll
            for (int off = 8; off > 0; off >>= 1)
                mx = fmaxf(mx, __shfl_xor_sync(0xffffffffu, mx, off));
            float mnew = fmaxf(mrow[r], mx);
            float corr = __expf(mrow[r] - mnew);
            float rs = 0.f;
            #pragma unroll
            for (int c = 0; c < 4; c++) {
                s[r][c] = __expf(s[r][c] - mnew);
                rs += s[r][c];
            }
            #pragma unroll
            for (int off = 8; off > 0; off >>= 1)
                rs += __shfl_xor_sync(0xffffffffu, rs, off);
            lrow[r] = lrow[r] * corr + rs;
            mrow[r] = mnew;
            #pragma unroll
            for (int c = 0; c < 4; c++) o[r][c] *= corr;
        }

        // stage P to smem for the PV product
        #pragma unroll
        for (int r = 0; r < 4; r++)
            #pragma unroll
            for (int c = 0; c < 4; c++)
                Ps[(ty * 4 + r) * 68 + tx * 4 + c] = s[r][c];
        __syncthreads();

        // O += P @ V
        #pragma unroll 8
        for (int cc = 0; cc < 64; cc++) {
            float a[4], b[4];
            #pragma unroll
            for (int r = 0; r < 4; r++) a[r] = Ps[(ty * 4 + r) * 68 + cc];
            #pragma unroll
            for (int c = 0; c < 4; c++) b[c] = Vs[cc * 68 + tx * 4 + c];
            #pragma unroll
            for (int r = 0; r < 4; r++)
                #pragma unroll
                for (int c = 0; c < 4; c++)
                    o[r][c] = fmaf(a[r], b[c], o[r][c]);
        }
    }

    // normalize + write context (L, E) layout
    #pragma unroll
    for (int r = 0; r < 4; r++) {
        float inv = 1.0f / lrow[r];
        #pragma unroll
        for (int c = 0; c < 4; c++)
            g_ctx[(i0 + ty * 4 + r) * EMB + h * HDIM + tx * 4 + c] = o[r][c] * inv;
    }
}

// ---------------------------------------------------------------------------
extern "C" void kernel_launch(void* const* d_in, const int* in_sizes, int n_in,
                              void* d_out, int out_size)
{
    const float* query = (const float*)d_in[0];
    const float* key   = (const float*)d_in[1];
    const float* value = (const float*)d_in[2];
    const int*   eid   = (const int*)d_in[3];
    const float* w_in  = (const float*)d_in[4];
    const float* b_in  = (const float*)d_in[5];
    const float* w_out = (const float*)d_in[6];
    const float* b_out = (const float*)d_in[7];
    const float* embK  = (const float*)d_in[8];
    float* out = (float*)d_out;

    float *qp, *kp, *vp, *ctxp;
    cudaGetSymbolAddress((void**)&qp,   g_q);
    cudaGetSymbolAddress((void**)&kp,   g_k);
    cudaGetSymbolAddress((void**)&vp,   g_v);
    cudaGetSymbolAddress((void**)&ctxp, g_ctx);

    dim3 gemm_grid(L_SEQ / 64, EMB / 64);

    // QKV projections (q scaled by 1/sqrt(64))
    gemm_abT<<<gemm_grid, 256>>>(query, w_in,                 b_in,           qp,
                                 L_SEQ, EMB, EMB, 0.125f);
    gemm_abT<<<gemm_grid, 256>>>(key,   w_in + EMB * EMB,     b_in + EMB,     kp,
                                 L_SEQ, EMB, EMB, 1.0f);
    gemm_abT<<<gemm_grid, 256>>>(value, w_in + 2 * EMB * EMB, b_in + 2 * EMB, vp,
                                 L_SEQ, EMB, EMB, 1.0f);

    // per-row per-head type scores (rank-10 edge bias LUT)
    type_scores_kernel<<<(NHEAD * L_SEQ) / 256, 256>>>(embK);

    // fused attention
    int smem_bytes = (4 * 64 * 68 + 64 * 16) * (int)sizeof(float);  // 73728
    cudaFuncSetAttribute(attn_kernel, cudaFuncAttributeMaxDynamicSharedMemorySize,
                         smem_bytes);
    dim3 attn_grid(L_SEQ / 64, NHEAD);
    attn_kernel<<<attn_grid, 256, smem_bytes>>>(eid);

    // output projection
    gemm_abT<<<gemm_grid, 256>>>(ctxp, w_out, b_out, out, L_SEQ, EMB, EMB, 1.0f);
}

// round 4
// speedup vs baseline: 1.3423x; 1.3423x over previous
#include <cuda_runtime.h>
#include <cuda_bf16.h>
#include <cstdint>

#define L_SEQ 2048
#define EMB   512
#define NHEAD 8
#define HDIM  64
#define NTYPE 10
#define KSPLIT 1536      // 3 * EMB  (activations [hi|lo|hi], weights [hi|hi|lo])

// ---------------------------------------------------------------------------
// Scratch (allocation-free rule: device globals)
// ---------------------------------------------------------------------------
__device__ float g_q[L_SEQ * EMB];
__device__ float g_k[L_SEQ * EMB];
__device__ float g_v[L_SEQ * EMB];
__device__ float g_ctx[L_SEQ * EMB];
__device__ float g_ts[NHEAD * L_SEQ * 16];

__device__ __nv_bfloat16 g_aq[L_SEQ * KSPLIT];
__device__ __nv_bfloat16 g_ak[L_SEQ * KSPLIT];
__device__ __nv_bfloat16 g_av[L_SEQ * KSPLIT];
__device__ __nv_bfloat16 g_actx[L_SEQ * KSPLIT];
__device__ __nv_bfloat16 g_wqkv[3 * EMB * KSPLIT];
__device__ __nv_bfloat16 g_wo[EMB * KSPLIT];
__device__ __nv_bfloat16 g_svt[NHEAD * 2 * HDIM * L_SEQ];  // [h][vh(64)|vl(64)][j]

// ---------------------------------------------------------------------------
// helpers
// ---------------------------------------------------------------------------
__device__ __forceinline__ uint32_t packbf(float lo, float hi) {
    uint32_t r;
    asm("cvt.rn.bf16x2.f32 %0, %1, %2;" : "=r"(r) : "f"(hi), "f"(lo));
    return r;
}
__device__ __forceinline__ void mma16816(float* d, const uint32_t* a,
                                         uint32_t b0, uint32_t b1) {
    asm volatile(
        "mma.sync.aligned.m16n8k16.row.col.f32.bf16.bf16.f32 "
        "{%0,%1,%2,%3}, {%4,%5,%6,%7}, {%8,%9}, {%0,%1,%2,%3};"
        : "+f"(d[0]), "+f"(d[1]), "+f"(d[2]), "+f"(d[3])
        : "r"(a[0]), "r"(a[1]), "r"(a[2]), "r"(a[3]), "r"(b0), "r"(b1));
}

// ---------------------------------------------------------------------------
// bf16 split kernels: x[.,512] -> y[.,1536]
//   hlh: [hi | lo | hi]   (activations)
//   hhl: [hi | hi | lo]   (weights / K-side)
// ---------------------------------------------------------------------------
__global__ __launch_bounds__(256) void split_hlh(const float* __restrict__ x,
                                                 __nv_bfloat16* __restrict__ y,
                                                 int total) {
    int idx = blockIdx.x * 256 + threadIdx.x;
    if (idx >= total) return;
    int r = idx >> 9, c = idx & 511;
    float v = x[idx];
    __nv_bfloat16 h = __float2bfloat16(v);
    __nv_bfloat16 l = __float2bfloat16(v - __bfloat162float(h));
    __nv_bfloat16* yr = y + (size_t)r * KSPLIT;
    yr[c] = h; yr[512 + c] = l; yr[1024 + c] = h;
}
__global__ __launch_bounds__(256) void split_hhl(const float* __restrict__ x,
                                                 __nv_bfloat16* __restrict__ y,
                                                 int total) {
    int idx = blockIdx.x * 256 + threadIdx.x;
    if (idx >= total) return;
    int r = idx >> 9, c = idx & 511;
    float v = x[idx];
    __nv_bfloat16 h = __float2bfloat16(v);
    __nv_bfloat16 l = __float2bfloat16(v - __bfloat162float(h));
    __nv_bfloat16* yr = y + (size_t)r * KSPLIT;
    yr[c] = h; yr[512 + c] = h; yr[1024 + c] = l;
}

// ---------------------------------------------------------------------------
// V split + transpose: g_v (L,512) f32 -> g_svt [h][vh|vl 128 rows][2048 j] bf16
// block = (jtile, head): 64 j x 64 d tile
// ---------------------------------------------------------------------------
__global__ __launch_bounds__(256) void v_split_transpose() {
    __shared__ float tile[64][68];
    int h = blockIdx.y, j0 = blockIdx.x * 64;
    int tid = threadIdx.x;
    {
        int row = tid >> 2, cg = (tid & 3) * 16;
        const float* src = g_v + (size_t)(j0 + row) * EMB + h * HDIM + cg;
        #pragma unroll
        for (int i = 0; i < 4; i++)
            *(float4*)&tile[row][cg + i * 4] = *(const float4*)(src + i * 4);
    }
    __syncthreads();
    int d = tid >> 2, jg = (tid & 3) * 16;
    uint32_t hw[8], lw[8];
    #pragma unroll
    for (int p = 0; p < 8; p++) {
        float v0 = tile[jg + 2 * p][d], v1 = tile[jg + 2 * p + 1][d];
        float h0 = __bfloat162float(__float2bfloat16(v0));
        float h1 = __bfloat162float(__float2bfloat16(v1));
        hw[p] = packbf(h0, h1);
        lw[p] = packbf(v0 - h0, v1 - h1);
    }
    __nv_bfloat16* dsth = g_svt + ((size_t)(h * 128 + d) * L_SEQ + j0 + jg);
    __nv_bfloat16* dstl = g_svt + ((size_t)(h * 128 + 64 + d) * L_SEQ + j0 + jg);
    *(uint4*)dsth       = make_uint4(hw[0], hw[1], hw[2], hw[3]);
    *(uint4*)(dsth + 8) = make_uint4(hw[4], hw[5], hw[6], hw[7]);
    *(uint4*)dstl       = make_uint4(lw[0], lw[1], lw[2], lw[3]);
    *(uint4*)(dstl + 8) = make_uint4(lw[4], lw[5], lw[6], lw[7]);
}

// ---------------------------------------------------------------------------
// mma.sync GEMM: C[128,128 tile] = scale*(A[128,1536] @ B[128,1536]^T + bias)
// 256 threads = 8 warps (2x4), warp tile 64x32
// ---------------------------------------------------------------------------
__device__ __forceinline__ void gemm_core(const __nv_bfloat16* __restrict__ A,
                                          const __nv_bfloat16* __restrict__ B,
                                          const float* __restrict__ bias,
                                          float* __restrict__ C, int ldc,
                                          int cn0, int m0, float scale) {
    __shared__ __nv_bfloat16 As[128 * 40];
    __shared__ __nv_bfloat16 Bs[128 * 40];
    int tid = threadIdx.x, wid = tid >> 5, lane = tid & 31;
    int gid = lane >> 2, qt = lane & 3;
    int wm = wid >> 2, wn = wid & 3;

    float acc[4][4][4] = {};
    int lrow = tid >> 1, lcol = (tid & 1) * 16;
    const __nv_bfloat16* Ap = A + (size_t)(m0 + lrow) * KSPLIT + lcol;
    const __nv_bfloat16* Bp = B + (size_t)lrow * KSPLIT + lcol;

    for (int kt = 0; kt < KSPLIT / 32; kt++) {
        __syncthreads();
        *(uint4*)&As[lrow * 40 + lcol]     = *(const uint4*)(Ap + kt * 32);
        *(uint4*)&As[lrow * 40 + lcol + 8] = *(const uint4*)(Ap + kt * 32 + 8);
        *(uint4*)&Bs[lrow * 40 + lcol]     = *(const uint4*)(Bp + kt * 32);
        *(uint4*)&Bs[lrow * 40 + lcol + 8] = *(const uint4*)(Bp + kt * 32 + 8);
        __syncthreads();
        #pragma unroll
        for (int kc = 0; kc < 2; kc++) {
            uint32_t a[4][4];
            #pragma unroll
            for (int mf = 0; mf < 4; mf++) {
                int r = wm * 64 + mf * 16 + gid;
                int c = kc * 16 + qt * 2;
                a[mf][0] = *(const uint32_t*)&As[r * 40 + c];
                a[mf][1] = *(const uint32_t*)&As[(r + 8) * 40 + c];
                a[mf][2] = *(const uint32_t*)&As[r * 40 + c + 8];
                a[mf][3] = *(const uint32_t*)&As[(r + 8) * 40 + c + 8];
            }
            #pragma unroll
            for (int nf = 0; nf < 4; nf++) {
                int n = wn * 32 + nf * 8 + gid;
                int c = kc * 16 + qt * 2;
                uint32_t b0 = *(const uint32_t*)&Bs[n * 40 + c];
                uint32_t b1 = *(const uint32_t*)&Bs[n * 40 + c + 8];
                #pragma unroll
                for (int mf = 0; mf < 4; mf++)
                    mma16816(acc[mf][nf], a[mf], b0, b1);
            }
        }
    }
    #pragma unroll
    for (int mf = 0; mf < 4; mf++) {
        int r = m0 + wm * 64 + mf * 16 + gid;
        #pragma unroll
        for (int nf = 0; nf < 4; nf++) {
            int cb = wn * 32 + nf * 8 + qt * 2;
            float b0 = __ldg(bias + cb), b1 = __ldg(bias + cb + 1);
            float2 v0 = make_float2(scale * (acc[mf][nf][0] + b0),
                                    scale * (acc[mf][nf][1] + b1));
            float2 v1 = make_float2(scale * (acc[mf][nf][2] + b0),
                                    scale * (acc[mf][nf][3] + b1));
            *(float2*)&C[(size_t)r * ldc + cn0 + cb]       = v0;
            *(float2*)&C[(size_t)(r + 8) * ldc + cn0 + cb] = v1;
        }
    }
}

__global__ __launch_bounds__(256) void gemm_qkv_kernel(const float* __restrict__ bias) {
    int m0 = blockIdx.x * 128;
    int nt = blockIdx.y;          // 0..11
    int sect = nt >> 2;
    const __nv_bfloat16* A = sect == 0 ? g_aq : (sect == 1 ? g_ak : g_av);
    float* C = sect == 0 ? g_q : (sect == 1 ? g_k : g_v);
    float scale = sect == 0 ? 0.125f : 1.0f;
    gemm_core(A, g_wqkv + (size_t)nt * 128 * KSPLIT, bias + nt * 128,
              C, EMB, (nt & 3) * 128, m0, scale);
}
__global__ __launch_bounds__(256) void gemm_out_kernel(const float* __restrict__ bias,
                                                       float* __restrict__ C) {
    gemm_core(g_actx, g_wo + (size_t)blockIdx.y * 128 * KSPLIT,
              bias + blockIdx.y * 128, C, EMB, blockIdx.y * 128,
              blockIdx.x * 128, 1.0f);
}

// ---------------------------------------------------------------------------
// type_scores[h,i,t] = sum_d q[i, h*64+d] * edge_embs[t,d]  — warp per (h,i)
// ---------------------------------------------------------------------------
__global__ __launch_bounds__(256) void type_scores_kernel(
    const float* __restrict__ edge_embs) {
    __shared__ float emb[NTYPE * HDIM];
    int tid = threadIdx.x;
    for (int i = tid; i < NTYPE * HDIM; i += 256) emb[i] = edge_embs[i];
    __syncthreads();
    int warp = blockIdx.x * 8 + (tid >> 5);
    int lane = tid & 31;
    int h = warp >> 11, i = warp & (L_SEQ - 1);
    float2 qv = *(const float2*)(g_q + (size_t)i * EMB + h * HDIM + lane * 2);
    float s[NTYPE];
    #pragma unroll
    for (int t = 0; t < NTYPE; t++) {
        float2 e = *(const float2*)(emb + t * HDIM + lane * 2);
        s[t] = qv.x * e.x + qv.y * e.y;
    }
    #pragma unroll
    for (int off = 16; off > 0; off >>= 1)
        #pragma unroll
        for (int t = 0; t < NTYPE; t++)
            s[t] += __shfl_xor_sync(0xffffffffu, s[t], off);
    if (lane == 0) {
        float* dst = g_ts + (size_t)warp * 16;
        #pragma unroll
        for (int t = 0; t < NTYPE; t++) dst[t] = s[t];
    }
}

// ---------------------------------------------------------------------------
// Flash attention with edge bias — mma.sync bf16 with 3-term splits.
// block = (i-tile 64, head), 128 threads = 4 warps x 16 rows.
// ---------------------------------------------------------------------------
#define AT_PITCH 136   // Qs/Ks bf16 pitch (128 data + 8 pad)
#define VT_PITCH 72    // Vt bf16 pitch (64 data + 8 pad)
#define SM_QS 0
#define SM_KS 17408
#define SM_VT 34816
#define SM_TS 53248
#define ATTN_SMEM 57344

__global__ __launch_bounds__(128) void attn_mma_kernel(const int* __restrict__ edge_id) {
    extern __shared__ char smb[];
    __nv_bfloat16* Qs = (__nv_bfloat16*)(smb + SM_QS);
    __nv_bfloat16* Ks = (__nv_bfloat16*)(smb + SM_KS);
    __nv_bfloat16* Vt = (__nv_bfloat16*)(smb + SM_VT);
    float* Ts = (float*)(smb + SM_TS);

    int h = blockIdx.y;
    int i0 = blockIdx.x * 64;
    int tid = threadIdx.x, wid = tid >> 5, lane = tid & 31;
    int gid = lane >> 2, qt = lane & 3;

    // Q tile: [row][qh(64)|ql(64)]; q split is hlh -> qh sect0, ql sect1
    // Each (row, half) copies 64 bf16 = 8 x uint4.
    {
        int row = tid >> 1, half = tid & 1;
        const __nv_bfloat16* src = g_aq + (size_t)(i0 + row) * KSPLIT + half * 512 + h * HDIM;
        uint4* d4 = (uint4*)(Qs + row * AT_PITCH + half * 64);
        const uint4* s4 = (const uint4*)src;
        #pragma unroll
        for (int i = 0; i < 8; i++) d4[i] = s4[i];
        const float* tsrc = g_ts + ((size_t)h * L_SEQ + i0 + row) * 16 + half * 8;
        *(float4*)(Ts + row * 16 + half * 8)     = *(const float4*)tsrc;
        *(float4*)(Ts + row * 16 + half * 8 + 4) = *(const float4*)(tsrc + 4);
    }

    float o[8][4] = {};
    float m0 = -1e30f, m1 = -1e30f, l0 = 0.f, l1 = 0.f;
    int r0loc = wid * 16 + gid;          // local row (0..63)
    const float* T0 = Ts + r0loc * 16;
    const float* T1 = T0 + 8 * 16;

    for (int jt = 0; jt < L_SEQ / 64; jt++) {
        int j0 = jt * 64;
        __syncthreads();
        // K tile: kh sect0, kl sect2 (hhl split) — 8 x uint4 per (row, half).
        {
            int row = tid >> 1, half = tid & 1;
            const __nv_bfloat16* src = g_ak + (size_t)(j0 + row) * KSPLIT + half * 1024 + h * HDIM;
            uint4* d4 = (uint4*)(Ks + row * AT_PITCH + half * 64);
            const uint4* s4 = (const uint4*)src;
            #pragma unroll
            for (int i = 0; i < 8; i++) d4[i] = s4[i];
            // V tile: 128 d-rows x 64 j — 8 x uint4 per d-row.
            const __nv_bfloat16* vs = g_svt + (size_t)(h * 128 + tid) * L_SEQ + j0;
            uint4* v4 = (uint4*)(Vt + tid * VT_PITCH);
            const uint4* vv = (const uint4*)vs;
            #pragma unroll
            for (int i = 0; i < 8; i++) v4[i] = vv[i];
        }
        __syncthreads();

        // ---- S = (qh+ql)·(kh+kl) via 3 terms ----
        float sa[8][4] = {};
        const int ta[3] = {0, 64, 0};
        const int tb[3] = {0, 0, 64};
        #pragma unroll
        for (int term = 0; term < 3; term++) {
            #pragma unroll
            for (int kc = 0; kc < 4; kc++) {
                uint32_t a[4];
                int ac = ta[term] + kc * 16 + qt * 2;
                a[0] = *(const uint32_t*)&Qs[r0loc * AT_PITCH + ac];
                a[1] = *(const uint32_t*)&Qs[(r0loc + 8) * AT_PITCH + ac];
                a[2] = *(const uint32_t*)&Qs[r0loc * AT_PITCH + ac + 8];
                a[3] = *(const uint32_t*)&Qs[(r0loc + 8) * AT_PITCH + ac + 8];
                #pragma unroll
                for (int nt = 0; nt < 8; nt++) {
                    int brow = nt * 8 + gid;
                    int bc = tb[term] + kc * 16 + qt * 2;
                    uint32_t b0 = *(const uint32_t*)&Ks[brow * AT_PITCH + bc];
                    uint32_t b1 = *(const uint32_t*)&Ks[brow * AT_PITCH + bc + 8];
                    mma16816(sa[nt], a, b0, b1);
                }
            }
        }

        // ---- edge bias ----
        int grow0 = i0 + r0loc, grow1 = grow0 + 8;
        #pragma unroll
        for (int nt = 0; nt < 8; nt++) {
            int col = j0 + nt * 8 + qt * 2;
            int2 e0 = *(const int2*)&edge_id[(size_t)grow0 * L_SEQ + col];
            int2 e1 = *(const int2*)&edge_id[(size_t)grow1 * L_SEQ + col];
            sa[nt][0] += T0[e0.x]; sa[nt][1] += T0[e0.y];
            sa[nt][2] += T1[e1.x]; sa[nt][3] += T1[e1.y];
        }

        // ---- online softmax ----
        float mx0 = -1e30f, mx1 = -1e30f;
        #pragma unroll
        for (int nt = 0; nt < 8; nt++) {
            mx0 = fmaxf(mx0, fmaxf(sa[nt][0], sa[nt][1]));
            mx1 = fmaxf(mx1, fmaxf(sa[nt][2], sa[nt][3]));
        }
        mx0 = fmaxf(mx0, __shfl_xor_sync(0xffffffffu, mx0, 1));
        mx0 = fmaxf(mx0, __shfl_xor_sync(0xffffffffu, mx0, 2));
        mx1 = fmaxf(mx1, __shfl_xor_sync(0xffffffffu, mx1, 1));
        mx1 = fmaxf(mx1, __shfl_xor_sync(0xffffffffu, mx1, 2));
        float mn0 = fmaxf(m0, mx0), mn1 = fmaxf(m1, mx1);
        float c0 = __expf(m0 - mn0), c1 = __expf(m1 - mn1);
        float rs0 = 0.f, rs1 = 0.f;
        #pragma unroll
        for (int nt = 0; nt < 8; nt++) {
            sa[nt][0] = __expf(sa[nt][0] - mn0);
            sa[nt][1] = __expf(sa[nt][1] - mn0);
            sa[nt][2] = __expf(sa[nt][2] - mn1);
            sa[nt][3] = __expf(sa[nt][3] - mn1);
            rs0 += sa[nt][0] + sa[nt][1];
            rs1 += sa[nt][2] + sa[nt][3];
        }
        rs0 += __shfl_xor_sync(0xffffffffu, rs0, 1);
        rs0 += __shfl_xor_sync(0xffffffffu, rs0, 2);
        rs1 += __shfl_xor_sync(0xffffffffu, rs1, 1);
        rs1 += __shfl_xor_sync(0xffffffffu, rs1, 2);
        l0 = l0 * c0 + rs0; l1 = l1 * c1 + rs1;
        m0 = mn0; m1 = mn1;
        #pragma unroll
        for (int dt = 0; dt < 8; dt++) {
            o[dt][0] *= c0; o[dt][1] *= c0;
            o[dt][2] *= c1; o[dt][3] *= c1;
        }

        // ---- P split into A-fragments ----
        uint32_t ph[4][4], pl[4][4];
        #pragma unroll
        for (int kc = 0; kc < 4; kc++) {
            #pragma unroll
            for (int half = 0; half < 2; half++) {    // tiles 2kc, 2kc+1
                const float* sv = sa[2 * kc + half];
                float h0 = __bfloat162float(__float2bfloat16(sv[0]));
                float h1 = __bfloat162float(__float2bfloat16(sv[1]));
                float h2 = __bfloat162float(__float2bfloat16(sv[2]));
                float h3 = __bfloat162float(__float2bfloat16(sv[3]));
                ph[kc][half]         = packbf(h0, h1);
                ph[kc][half + 2]     = packbf(h2, h3);
                pl[kc][half]         = packbf(sv[0] - h0, sv[1] - h1);
                pl[kc][half + 2]     = packbf(sv[2] - h2, sv[3] - h3);
            }
        }
        // fix fragment order: a = {row,k-tile0}, {row+8,k-tile0}, {row,k-tile1}, {row+8,k-tile1}
        #pragma unroll
        for (int kc = 0; kc < 4; kc++) {
            uint32_t t;
            t = ph[kc][1]; ph[kc][1] = ph[kc][2]; ph[kc][2] = t;
            t = pl[kc][1]; pl[kc][1] = pl[kc][2]; pl[kc][2] = t;
        }

        // ---- O += ph·vh + pl·vh + ph·vl ----
        #pragma unroll
        for (int kc = 0; kc < 4; kc++) {
            int vc = kc * 16 + qt * 2;
            #pragma unroll
            for (int dt = 0; dt < 8; dt++) {
                int vrh = dt * 8 + gid;
                uint32_t bh0 = *(const uint32_t*)&Vt[vrh * VT_PITCH + vc];
                uint32_t bh1 = *(const uint32_t*)&Vt[vrh * VT_PITCH + vc + 8];
                mma16816(o[dt], ph[kc], bh0, bh1);
                mma16816(o[dt], pl[kc], bh0, bh1);
                uint32_t bl0 = *(const uint32_t*)&Vt[(64 + vrh) * VT_PITCH + vc];
                uint32_t bl1 = *(const uint32_t*)&Vt[(64 + vrh) * VT_PITCH + vc + 8];
                mma16816(o[dt], ph[kc], bl0, bl1);
            }
        }
    }

    float inv0 = 1.0f / l0, inv1 = 1.0f / l1;
    #pragma unroll
    for (int dt = 0; dt < 8; dt++) {
        int cb = h * HDIM + dt * 8 + qt * 2;
        *(float2*)&g_ctx[(size_t)(i0 + r0loc) * EMB + cb] =
            make_float2(o[dt][0] * inv0, o[dt][1] * inv0);
        *(float2*)&g_ctx[(size_t)(i0 + r0loc + 8) * EMB + cb] =
            make_float2(o[dt][2] * inv1, o[dt][3] * inv1);
    }
}

// ---------------------------------------------------------------------------
extern "C" void kernel_launch(void* const* d_in, const int* in_sizes, int n_in,
                              void* d_out, int out_size)
{
    const float* query = (const float*)d_in[0];
    const float* key   = (const float*)d_in[1];
    const float* value = (const float*)d_in[2];
    const int*   eid   = (const int*)d_in[3];
    const float* w_in  = (const float*)d_in[4];
    const float* b_in  = (const float*)d_in[5];
    const float* w_out = (const float*)d_in[6];
    const float* b_out = (const float*)d_in[7];
    const float* embK  = (const float*)d_in[8];
    float* out = (float*)d_out;

    float *qp, *kp, *vp, *ctxp;
    __nv_bfloat16 *aq, *ak, *av, *actx, *wqkv, *wo;
    cudaGetSymbolAddress((void**)&qp,   g_q);
    cudaGetSymbolAddress((void**)&kp,   g_k);
    cudaGetSymbolAddress((void**)&vp,   g_v);
    cudaGetSymbolAddress((void**)&ctxp, g_ctx);
    cudaGetSymbolAddress((void**)&aq,   g_aq);
    cudaGetSymbolAddress((void**)&ak,   g_ak);
    cudaGetSymbolAddress((void**)&av,   g_av);
    cudaGetSymbolAddress((void**)&actx, g_actx);
    cudaGetSymbolAddress((void**)&wqkv, g_wqkv);
    cudaGetSymbolAddress((void**)&wo,   g_wo);

    int actTotal = L_SEQ * EMB;
    int wTotal   = 3 * EMB * EMB;
    int woTotal  = EMB * EMB;

    // 1. splits of raw inputs + weights
    split_hlh<<<(actTotal + 255) / 256, 256>>>(query, aq, actTotal);
    split_hlh<<<(actTotal + 255) / 256, 256>>>(key,   ak, actTotal);
    split_hlh<<<(actTotal + 255) / 256, 256>>>(value, av, actTotal);
    split_hhl<<<(wTotal  + 255) / 256, 256>>>(w_in,  wqkv, wTotal);
    split_hhl<<<(woTotal + 255) / 256, 256>>>(w_out, wo,   woTotal);

    // 2. QKV projection (tensor-core)
    dim3 qkv_grid(L_SEQ / 128, 12);
    gemm_qkv_kernel<<<qkv_grid, 256>>>(b_in);

    // 3. edge-type score LUT
    type_scores_kernel<<<(NHEAD * L_SEQ) / 8, 256>>>(embK);

    // 4. re-split projected q/k (reuse buffers) + v transpose/split
    split_hlh<<<(actTotal + 255) / 256, 256>>>(qp, aq, actTotal);
    split_hhl<<<(actTotal + 255) / 256, 256>>>(kp, ak, actTotal);
    dim3 vt_grid(L_SEQ / 64, NHEAD);
    v_split_transpose<<<vt_grid, 256>>>();

    // 5. fused flash attention with edge bias (tensor-core)
    cudaFuncSetAttribute(attn_mma_kernel, cudaFuncAttributeMaxDynamicSharedMemorySize,
                         ATTN_SMEM);
    dim3 attn_grid(L_SEQ / 64, NHEAD);
    attn_mma_kernel<<<attn_grid, 128, ATTN_SMEM>>>(eid);

    // 6. out projection (tensor-core)
    split_hlh<<<(actTotal + 255) / 256, 256>>>(ctxp, actx, actTotal);
    dim3 out_grid(L_SEQ / 128, 4);
    gemm_out_kernel<<<out_grid, 256>>>(b_out, out);
}

// round 5
// speedup vs baseline: 1.5364x; 1.1446x over previous
#include <cuda_runtime.h>
#include <cuda_bf16.h>
#include <cstdint>

#define L_SEQ 2048
#define EMB   512
#define NHEAD 8
#define HDIM  64
#define NTYPE 10
#define KSPLIT 1536      // 3 * EMB  (activations [hi|lo|hi], weights [hi|hi|lo])

// ---------------------------------------------------------------------------
// Scratch (allocation-free rule: device globals)
// ---------------------------------------------------------------------------
__device__ float g_v[L_SEQ * EMB];
__device__ float g_ts[NHEAD * L_SEQ * 16];

__device__ __nv_bfloat16 g_aq[L_SEQ * KSPLIT];   // split input query
__device__ __nv_bfloat16 g_ak[L_SEQ * KSPLIT];   // split input key
__device__ __nv_bfloat16 g_av[L_SEQ * KSPLIT];   // split input value
__device__ __nv_bfloat16 g_wqkv[3 * EMB * KSPLIT];
__device__ __nv_bfloat16 g_wo[EMB * KSPLIT];
__device__ __nv_bfloat16 g_sq[L_SEQ * KSPLIT];   // projected q, hlh split
__device__ __nv_bfloat16 g_sk[L_SEQ * KSPLIT];   // projected k, hhl split
__device__ __nv_bfloat16 g_actx[L_SEQ * KSPLIT]; // attention ctx, hlh split
__device__ __nv_bfloat16 g_svt[NHEAD * 2 * HDIM * L_SEQ];  // [h][vh|vl][j]

// ---------------------------------------------------------------------------
// helpers
// ---------------------------------------------------------------------------
__device__ __forceinline__ uint32_t packbf(float lo, float hi) {
    uint32_t r;
    asm("cvt.rn.bf16x2.f32 %0, %1, %2;" : "=r"(r) : "f"(hi), "f"(lo));
    return r;
}
__device__ __forceinline__ uint32_t smem_to_u32(const void* p) {
    uint32_t a;
    asm("{ .reg .u64 t; cvta.to.shared.u64 t, %1; cvt.u32.u64 %0, t; }"
        : "=r"(a) : "l"(p));
    return a;
}
__device__ __forceinline__ void mma16816(float* d, const uint32_t* a,
                                         uint32_t b0, uint32_t b1) {
    asm volatile(
        "mma.sync.aligned.m16n8k16.row.col.f32.bf16.bf16.f32 "
        "{%0,%1,%2,%3}, {%4,%5,%6,%7}, {%8,%9}, {%0,%1,%2,%3};"
        : "+f"(d[0]), "+f"(d[1]), "+f"(d[2]), "+f"(d[3])
        : "r"(a[0]), "r"(a[1]), "r"(a[2]), "r"(a[3]), "r"(b0), "r"(b1));
}
__device__ __forceinline__ void cp16(uint32_t s, const void* g) {
    asm volatile("cp.async.cg.shared.global [%0], [%1], 16;"
                 :: "r"(s), "l"(g) : "memory");
}
#define CP_COMMIT asm volatile("cp.async.commit_group;" ::: "memory")

// hlh (mode 1) / hhl (mode 2) split store of a col pair
__device__ __forceinline__ void store_split(__nv_bfloat16* d, float v0, float v1,
                                            int mode) {
    float h0 = __bfloat162float(__float2bfloat16(v0));
    float h1 = __bfloat162float(__float2bfloat16(v1));
    uint32_t hh = packbf(h0, h1), ll = packbf(v0 - h0, v1 - h1);
    *(uint32_t*)d          = hh;
    *(uint32_t*)(d + 512)  = (mode == 1) ? ll : hh;
    *(uint32_t*)(d + 1024) = (mode == 1) ? hh : ll;
}

// ---------------------------------------------------------------------------
// bf16 input split kernels: x[.,512] -> y[.,1536]
// ---------------------------------------------------------------------------
__global__ __launch_bounds__(256) void split_hlh(const float* __restrict__ x,
                                                 __nv_bfloat16* __restrict__ y,
                                                 int total) {
    int idx = blockIdx.x * 256 + threadIdx.x;
    if (idx >= total) return;
    int r = idx >> 9, c = idx & 511;
    float v = x[idx];
    __nv_bfloat16 h = __float2bfloat16(v);
    __nv_bfloat16 l = __float2bfloat16(v - __bfloat162float(h));
    __nv_bfloat16* yr = y + (size_t)r * KSPLIT;
    yr[c] = h; yr[512 + c] = l; yr[1024 + c] = h;
}
__global__ __launch_bounds__(256) void split_hhl(const float* __restrict__ x,
                                                 __nv_bfloat16* __restrict__ y,
                                                 int total) {
    int idx = blockIdx.x * 256 + threadIdx.x;
    if (idx >= total) return;
    int r = idx >> 9, c = idx & 511;
    float v = x[idx];
    __nv_bfloat16 h = __float2bfloat16(v);
    __nv_bfloat16 l = __float2bfloat16(v - __bfloat162float(h));
    __nv_bfloat16* yr = y + (size_t)r * KSPLIT;
    yr[c] = h; yr[512 + c] = h; yr[1024 + c] = l;
}

// ---------------------------------------------------------------------------
// V split + transpose: g_v (L,512) f32 -> g_svt [h][vh|vl 128 rows][2048 j]
// ---------------------------------------------------------------------------
__global__ __launch_bounds__(256) void v_split_transpose() {
    __shared__ float tile[64][68];
    int h = blockIdx.y, j0 = blockIdx.x * 64;
    int tid = threadIdx.x;
    {
        int row = tid >> 2, cg = (tid & 3) * 16;
        const float* src = g_v + (size_t)(j0 + row) * EMB + h * HDIM + cg;
        #pragma unroll
        for (int i = 0; i < 4; i++)
            *(float4*)&tile[row][cg + i * 4] = *(const float4*)(src + i * 4);
    }
    __syncthreads();
    int d = tid >> 2, jg = (tid & 3) * 16;
    uint32_t hw[8], lw[8];
    #pragma unroll
    for (int p = 0; p < 8; p++) {
        float v0 = tile[jg + 2 * p][d], v1 = tile[jg + 2 * p + 1][d];
        float h0 = __bfloat162float(__float2bfloat16(v0));
        float h1 = __bfloat162float(__float2bfloat16(v1));
        hw[p] = packbf(h0, h1);
        lw[p] = packbf(v0 - h0, v1 - h1);
    }
    __nv_bfloat16* dsth = g_svt + ((size_t)(h * 128 + d) * L_SEQ + j0 + jg);
    __nv_bfloat16* dstl = g_svt + ((size_t)(h * 128 + 64 + d) * L_SEQ + j0 + jg);
    *(uint4*)dsth       = make_uint4(hw[0], hw[1], hw[2], hw[3]);
    *(uint4*)(dsth + 8) = make_uint4(hw[4], hw[5], hw[6], hw[7]);
    *(uint4*)dstl       = make_uint4(lw[0], lw[1], lw[2], lw[3]);
    *(uint4*)(dstl + 8) = make_uint4(lw[4], lw[5], lw[6], lw[7]);
}

// ---------------------------------------------------------------------------
// mma.sync GEMM, cp.async double-buffered.
// 256 threads = 8 warps (2x4), warp tile 64x32, block tile 128x128, K=1536.
// mode 0: fp32 out (ldc=EMB); mode 1: hlh split bf16; mode 2: hhl split bf16.
// ---------------------------------------------------------------------------
__device__ __forceinline__ void gemm_core(const __nv_bfloat16* __restrict__ A,
                                          const __nv_bfloat16* __restrict__ B,
                                          const float* __restrict__ bias,
                                          float* __restrict__ Cf,
                                          __nv_bfloat16* __restrict__ Cs,
                                          int cn0, int m0, float scale, int mode) {
    __shared__ __nv_bfloat16 As[2][128 * 40];
    __shared__ __nv_bfloat16 Bs[2][128 * 40];
    int tid = threadIdx.x, wid = tid >> 5, lane = tid & 31;
    int gid = lane >> 2, qt = lane & 3;
    int wm = wid >> 2, wn = wid & 3;

    float acc[4][4][4] = {};
    int lrow = tid >> 1, lcol = (tid & 1) * 16;
    const __nv_bfloat16* Ap = A + (size_t)(m0 + lrow) * KSPLIT + lcol;
    const __nv_bfloat16* Bp = B + (size_t)lrow * KSPLIT + lcol;
    uint32_t sA[2] = {smem_to_u32(&As[0][lrow * 40 + lcol]),
                      smem_to_u32(&As[1][lrow * 40 + lcol])};
    uint32_t sB[2] = {smem_to_u32(&Bs[0][lrow * 40 + lcol]),
                      smem_to_u32(&Bs[1][lrow * 40 + lcol])};

    cp16(sA[0], Ap); cp16(sA[0] + 16, Ap + 8);
    cp16(sB[0], Bp); cp16(sB[0] + 16, Bp + 8);
    CP_COMMIT;

    for (int kt = 0; kt < KSPLIT / 32; kt++) {
        int cur = kt & 1;
        if (kt + 1 < KSPLIT / 32) {
            int nx = cur ^ 1;
            const __nv_bfloat16* a = Ap + (kt + 1) * 32;
            const __nv_bfloat16* b = Bp + (kt + 1) * 32;
            cp16(sA[nx], a); cp16(sA[nx] + 16, a + 8);
            cp16(sB[nx], b); cp16(sB[nx] + 16, b + 8);
            CP_COMMIT;
            asm volatile("cp.async.wait_group 1;" ::: "memory");
        } else {
            asm volatile("cp.async.wait_group 0;" ::: "memory");
        }
        __syncthreads();
        #pragma unroll
        for (int kc = 0; kc < 2; kc++) {
            uint32_t a[4][4];
            #pragma unroll
            for (int mf = 0; mf < 4; mf++) {
                int r = wm * 64 + mf * 16 + gid;
                int c = kc * 16 + qt * 2;
                a[mf][0] = *(const uint32_t*)&As[cur][r * 40 + c];
                a[mf][1] = *(const uint32_t*)&As[cur][(r + 8) * 40 + c];
                a[mf][2] = *(const uint32_t*)&As[cur][r * 40 + c + 8];
                a[mf][3] = *(const uint32_t*)&As[cur][(r + 8) * 40 + c + 8];
            }
            #pragma unroll
            for (int nf = 0; nf < 4; nf++) {
                int n = wn * 32 + nf * 8 + gid;
                int c = kc * 16 + qt * 2;
                uint32_t b0 = *(const uint32_t*)&Bs[cur][n * 40 + c];
                uint32_t b1 = *(const uint32_t*)&Bs[cur][n * 40 + c + 8];
                #pragma unroll
                for (int mf = 0; mf < 4; mf++)
                    mma16816(acc[mf][nf], a[mf], b0, b1);
            }
        }
        __syncthreads();
    }
    #pragma unroll
    for (int mf = 0; mf < 4; mf++) {
        int r = m0 + wm * 64 + mf * 16 + gid;
        #pragma unroll
        for (int nf = 0; nf < 4; nf++) {
            int cb = wn * 32 + nf * 8 + qt * 2;
            float b0 = __ldg(bias + cb), b1 = __ldg(bias + cb + 1);
            float v00 = scale * (acc[mf][nf][0] + b0);
            float v01 = scale * (acc[mf][nf][1] + b1);
            float v10 = scale * (acc[mf][nf][2] + b0);
            float v11 = scale * (acc[mf][nf][3] + b1);
            int col = cn0 + cb;
            if (mode == 0) {
                *(float2*)&Cf[(size_t)r * EMB + col]       = make_float2(v00, v01);
                *(float2*)&Cf[(size_t)(r + 8) * EMB + col] = make_float2(v10, v11);
            } else {
                store_split(Cs + (size_t)r * KSPLIT + col, v00, v01, mode);
                store_split(Cs + (size_t)(r + 8) * KSPLIT + col, v10, v11, mode);
            }
        }
    }
}

__global__ __launch_bounds__(256) void gemm_qkv_kernel(const float* __restrict__ bias) {
    int m0 = blockIdx.x * 128;
    int nt = blockIdx.y;          // 0..11
    int sect = nt >> 2;
    int cn0 = (nt & 3) * 128;
    const __nv_bfloat16* Bw = g_wqkv + (size_t)nt * 128 * KSPLIT;
    if (sect == 0)
        gemm_core(g_aq, Bw, bias + nt * 128, nullptr, g_sq, cn0, m0, 0.125f, 1);
    else if (sect == 1)
        gemm_core(g_ak, Bw, bias + nt * 128, nullptr, g_sk, cn0, m0, 1.0f, 2);
    else
        gemm_core(g_av, Bw, bias + nt * 128, g_v, nullptr, cn0, m0, 1.0f, 0);
}
__global__ __launch_bounds__(256) void gemm_out_kernel(const float* __restrict__ bias,
                                                       float* __restrict__ C) {
    gemm_core(g_actx, g_wo + (size_t)blockIdx.y * 128 * KSPLIT,
              bias + blockIdx.y * 128, C, nullptr, blockIdx.y * 128,
              blockIdx.x * 128, 1.0f, 0);
}

// ---------------------------------------------------------------------------
// type_scores[h,i,t] = sum_d q[i,h*64+d] * edge_embs[t,d]; q = hi+lo from g_sq
// ---------------------------------------------------------------------------
__global__ __launch_bounds__(256) void type_scores_kernel(
    const float* __restrict__ edge_embs) {
    __shared__ float emb[NTYPE * HDIM];
    int tid = threadIdx.x;
    for (int i = tid; i < NTYPE * HDIM; i += 256) emb[i] = edge_embs[i];
    __syncthreads();
    int warp = blockIdx.x * 8 + (tid >> 5);
    int lane = tid & 31;
    int h = warp >> 11, i = warp & (L_SEQ - 1);
    const __nv_bfloat16* qr = g_sq + (size_t)i * KSPLIT + h * HDIM + lane * 2;
    float2 qh = __bfloat1622float2(*(const __nv_bfloat162*)qr);
    float2 ql = __bfloat1622float2(*(const __nv_bfloat162*)(qr + 512));
    float2 qv = make_float2(qh.x + ql.x, qh.y + ql.y);
    float s[NTYPE];
    #pragma unroll
    for (int t = 0; t < NTYPE; t++) {
        float2 e = *(const float2*)(emb + t * HDIM + lane * 2);
        s[t] = qv.x * e.x + qv.y * e.y;
    }
    #pragma unroll
    for (int off = 16; off > 0; off >>= 1)
        #pragma unroll
        for (int t = 0; t < NTYPE; t++)
            s[t] += __shfl_xor_sync(0xffffffffu, s[t], off);
    if (lane == 0) {
        float* dst = g_ts + (size_t)warp * 16;
        #pragma unroll
        for (int t = 0; t < NTYPE; t++) dst[t] = s[t];
    }
}

// ---------------------------------------------------------------------------
// Flash attention, 2-way j-split: 8 warps = 2 groups x 4 warps.
// Group g owns its K/V smem buffers, processes jt = 2t+g with named barriers.
// Partial (m,l,O) combined in smem at the end; hlh-split ctx written directly.
// ---------------------------------------------------------------------------
#define AT_PITCH 136   // bf16 pitch (128 data + 8 pad)
#define VT_PITCH 72
#define SM_QS 0                         // 64*136*2      = 17408
#define SM_KS 17408                     // 2 * 17408     -> 52224
#define SM_VT 52224                     // 2 * 18432     -> 89088
#define SM_TS 89088                     // 64*16*4       -> 93184
#define ATTN_SMEM 93184

__global__ __launch_bounds__(256) void attn_mma_kernel(const int* __restrict__ edge_id) {
    extern __shared__ char smb[];
    __nv_bfloat16* Qs = (__nv_bfloat16*)(smb + SM_QS);
    float* Ts = (float*)(smb + SM_TS);

    int h = blockIdx.y;
    int i0 = blockIdx.x * 64;
    int tid = threadIdx.x, wid = tid >> 5, lane = tid & 31;
    int grp = wid >> 2, wg = wid & 3, gtid = tid & 127;
    int gid = lane >> 2, qt = lane & 3;
    __nv_bfloat16* Ks = (__nv_bfloat16*)(smb + SM_KS + grp * 17408);
    __nv_bfloat16* Vt = (__nv_bfloat16*)(smb + SM_VT + grp * 18432);

    // Q tile [row][qh|ql] + type-score LUT (all 256 threads)
    {
        int row = tid >> 2, q = tid & 3;
        const __nv_bfloat16* src = g_sq + (size_t)(i0 + row) * KSPLIT
                                   + (q >> 1) * 512 + h * HDIM + (q & 1) * 32;
        uint4* d4 = (uint4*)(Qs + row * AT_PITCH + q * 32);
        const uint4* s4 = (const uint4*)src;
        d4[0] = s4[0]; d4[1] = s4[1]; d4[2] = s4[2]; d4[3] = s4[3];
        *(float4*)(Ts + row * 16 + q * 4) =
            *(const float4*)(g_ts + ((size_t)h * L_SEQ + i0 + row) * 16 + q * 4);
    }
    __syncthreads();

    float o[8][4] = {};
    float rm0 = -1e30f, rm1 = -1e30f, rl0 = 0.f, rl1 = 0.f;
    int r0loc = wg * 16 + gid;
    const float* T0 = Ts + r0loc * 16;
    const float* T1 = T0 + 8 * 16;
    const int bid = grp + 1;

    for (int t = 0; t < 16; t++) {
        int j0 = (2 * t + grp) * 64;
        asm volatile("bar.sync %0, 128;" :: "r"(bid) : "memory");
        {   // group-local K/V tile load (128 threads)
            int row = gtid >> 1, half = gtid & 1;
            const __nv_bfloat16* src = g_sk + (size_t)(j0 + row) * KSPLIT
                                       + half * 1024 + h * HDIM;
            uint4* d4 = (uint4*)(Ks + row * AT_PITCH + half * 64);
            const uint4* s4 = (const uint4*)src;
            #pragma unroll
            for (int i = 0; i < 8; i++) d4[i] = s4[i];
            const __nv_bfloat16* vs = g_svt + (size_t)(h * 128 + gtid) * L_SEQ + j0;
            uint4* v4 = (uint4*)(Vt + gtid * VT_PITCH);
            const uint4* vv = (const uint4*)vs;
            #pragma unroll
            for (int i = 0; i < 8; i++) v4[i] = vv[i];
        }
        asm volatile("bar.sync %0, 128;" :: "r"(bid) : "memory");

        // ---- S = qh·kh + ql·kh + qh·kl ----
        float sa[8][4] = {};
        const int ta[3] = {0, 64, 0};
        const int tb[3] = {0, 0, 64};
        #pragma unroll
        for (int term = 0; term < 3; term++) {
            #pragma unroll
            for (int kc = 0; kc < 4; kc++) {
                uint32_t a[4];
                int ac = ta[term] + kc * 16 + qt * 2;
                a[0] = *(const uint32_t*)&Qs[r0loc * AT_PITCH + ac];
                a[1] = *(const uint32_t*)&Qs[(r0loc + 8) * AT_PITCH + ac];
                a[2] = *(const uint32_t*)&Qs[r0loc * AT_PITCH + ac + 8];
                a[3] = *(const uint32_t*)&Qs[(r0loc + 8) * AT_PITCH + ac + 8];
                #pragma unroll
                for (int nt = 0; nt < 8; nt++) {
                    int brow = nt * 8 + gid;
                    int bc = tb[term] + kc * 16 + qt * 2;
                    uint32_t b0 = *(const uint32_t*)&Ks[brow * AT_PITCH + bc];
                    uint32_t b1 = *(const uint32_t*)&Ks[brow * AT_PITCH + bc + 8];
                    mma16816(sa[nt], a, b0, b1);
                }
            }
        }

        // ---- edge bias ----
        int grow0 = i0 + r0loc, grow1 = grow0 + 8;
        #pragma unroll
        for (int nt = 0; nt < 8; nt++) {
            int col = j0 + nt * 8 + qt * 2;
            int2 e0 = *(const int2*)&edge_id[(size_t)grow0 * L_SEQ + col];
            int2 e1 = *(const int2*)&edge_id[(size_t)grow1 * L_SEQ + col];
            sa[nt][0] += T0[e0.x]; sa[nt][1] += T0[e0.y];
            sa[nt][2] += T1[e1.x]; sa[nt][3] += T1[e1.y];
        }

        // ---- online softmax ----
        float mx0 = -1e30f, mx1 = -1e30f;
        #pragma unroll
        for (int nt = 0; nt < 8; nt++) {
            mx0 = fmaxf(mx0, fmaxf(sa[nt][0], sa[nt][1]));
            mx1 = fmaxf(mx1, fmaxf(sa[nt][2], sa[nt][3]));
        }
        mx0 = fmaxf(mx0, __shfl_xor_sync(0xffffffffu, mx0, 1));
        mx0 = fmaxf(mx0, __shfl_xor_sync(0xffffffffu, mx0, 2));
        mx1 = fmaxf(mx1, __shfl_xor_sync(0xffffffffu, mx1, 1));
        mx1 = fmaxf(mx1, __shfl_xor_sync(0xffffffffu, mx1, 2));
        float mn0 = fmaxf(rm0, mx0), mn1 = fmaxf(rm1, mx1);
        float c0 = __expf(rm0 - mn0), c1 = __expf(rm1 - mn1);
        float rs0 = 0.f, rs1 = 0.f;
        #pragma unroll
        for (int nt = 0; nt < 8; nt++) {
            sa[nt][0] = __expf(sa[nt][0] - mn0);
            sa[nt][1] = __expf(sa[nt][1] - mn0);
            sa[nt][2] = __expf(sa[nt][2] - mn1);
            sa[nt][3] = __expf(sa[nt][3] - mn1);
            rs0 += sa[nt][0] + sa[nt][1];
            rs1 += sa[nt][2] + sa[nt][3];
        }
        rs0 += __shfl_xor_sync(0xffffffffu, rs0, 1);
        rs0 += __shfl_xor_sync(0xffffffffu, rs0, 2);
        rs1 += __shfl_xor_sync(0xffffffffu, rs1, 1);
        rs1 += __shfl_xor_sync(0xffffffffu, rs1, 2);
        rl0 = rl0 * c0 + rs0; rl1 = rl1 * c1 + rs1;
        rm0 = mn0; rm1 = mn1;
        #pragma unroll
        for (int dt = 0; dt < 8; dt++) {
            o[dt][0] *= c0; o[dt][1] *= c0;
            o[dt][2] *= c1; o[dt][3] *= c1;
        }

        // ---- PV: per-kc P split (short live range), O += ph·vh+pl·vh+ph·vl ----
        #pragma unroll
        for (int kc = 0; kc < 4; kc++) {
            const float* t0v = sa[2 * kc];
            const float* t1v = sa[2 * kc + 1];
            float h00 = __bfloat162float(__float2bfloat16(t0v[0]));
            float h01 = __bfloat162float(__float2bfloat16(t0v[1]));
            float h02 = __bfloat162float(__float2bfloat16(t0v[2]));
            float h03 = __bfloat162float(__float2bfloat16(t0v[3]));
            float h10 = __bfloat162float(__float2bfloat16(t1v[0]));
            float h11 = __bfloat162float(__float2bfloat16(t1v[1]));
            float h12 = __bfloat162float(__float2bfloat16(t1v[2]));
            float h13 = __bfloat162float(__float2bfloat16(t1v[3]));
            uint32_t ph[4], pl[4];
            ph[0] = packbf(h00, h01); ph[1] = packbf(h02, h03);
            ph[2] = packbf(h10, h11); ph[3] = packbf(h12, h13);
            pl[0] = packbf(t0v[0] - h00, t0v[1] - h01);
            pl[1] = packbf(t0v[2] - h02, t0v[3] - h03);
            pl[2] = packbf(t1v[0] - h10, t1v[1] - h11);
            pl[3] = packbf(t1v[2] - h12, t1v[3] - h13);
            int vc = kc * 16 + qt * 2;
            #pragma unroll
            for (int dt = 0; dt < 8; dt++) {
                int vrh = dt * 8 + gid;
                uint32_t bh0 = *(const uint32_t*)&Vt[vrh * VT_PITCH + vc];
                uint32_t bh1 = *(const uint32_t*)&Vt[vrh * VT_PITCH + vc + 8];
                mma16816(o[dt], ph, bh0, bh1);
                mma16816(o[dt], pl, bh0, bh1);
                uint32_t bl0 = *(const uint32_t*)&Vt[(64 + vrh) * VT_PITCH + vc];
                uint32_t bl1 = *(const uint32_t*)&Vt[(64 + vrh) * VT_PITCH + vc + 8];
                mma16816(o[dt], ph, bl0, bl1);
            }
        }
    }

    // ---- combine the two groups' partial softmax states ----
    __syncthreads();
    float* co = (float*)(smb + SM_KS);            // [64][66] pitch 66
    float* cm = (float*)(smb + SM_KS + 16896);    // [64]
    float* cl = (float*)(smb + SM_KS + 17152);    // [64]
    if (grp == 1) {
        if (qt == 0) {
            cm[r0loc] = rm0; cm[r0loc + 8] = rm1;
            cl[r0loc] = rl0; cl[r0loc + 8] = rl1;
        }
        #pragma unroll
        for (int dt = 0; dt < 8; dt++) {
            int c = dt * 8 + qt * 2;
            *(float2*)&co[r0loc * 66 + c]       = make_float2(o[dt][0], o[dt][1]);
            *(float2*)&co[(r0loc + 8) * 66 + c] = make_float2(o[dt][2], o[dt][3]);
        }
    }
    __syncthreads();
    if (grp == 0) {
        float m1a = cm[r0loc], l1a = cl[r0loc];
        float m1b = cm[r0loc + 8], l1b = cl[r0loc + 8];
        float M0 = fmaxf(rm0, m1a), M1 = fmaxf(rm1, m1b);
        float a0 = __expf(rm0 - M0), b0 = __expf(m1a - M0);
        float a1 = __expf(rm1 - M1), b1 = __expf(m1b - M1);
        float inv0 = 1.0f / (rl0 * a0 + l1a * b0);
        float inv1 = 1.0f / (rl1 * a1 + l1b * b1);
        __nv_bfloat16* dst0 = g_actx + (size_t)(i0 + r0loc) * KSPLIT + h * HDIM;
        __nv_bfloat16* dst1 = g_actx + (size_t)(i0 + r0loc + 8) * KSPLIT + h * HDIM;
        #pragma unroll
        for (int dt = 0; dt < 8; dt++) {
            int c = dt * 8 + qt * 2;
            float v0 = (o[dt][0] * a0 + co[r0loc * 66 + c] * b0) * inv0;
            float v1 = (o[dt][1] * a0 + co[r0loc * 66 + c + 1] * b0) * inv0;
            float w0 = (o[dt][2] * a1 + co[(r0loc + 8) * 66 + c] * b1) * inv1;
            float w1 = (o[dt][3] * a1 + co[(r0loc + 8) * 66 + c + 1] * b1) * inv1;
            store_split(dst0 + c, v0, v1, 1);
            store_split(dst1 + c, w0, w1, 1);
        }
    }
}

// ---------------------------------------------------------------------------
extern "C" void kernel_launch(void* const* d_in, const int* in_sizes, int n_in,
                              void* d_out, int out_size)
{
    const float* query = (const float*)d_in[0];
    const float* key   = (const float*)d_in[1];
    const float* value = (const float*)d_in[2];
    const int*   eid   = (const int*)d_in[3];
    const float* w_in  = (const float*)d_in[4];
    const float* b_in  = (const float*)d_in[5];
    const float* w_out = (const float*)d_in[6];
    const float* b_out = (const float*)d_in[7];
    const float* embK  = (const float*)d_in[8];
    float* out = (float*)d_out;

    __nv_bfloat16 *aq, *ak, *av, *wqkv, *wo;
    cudaGetSymbolAddress((void**)&aq,   g_aq);
    cudaGetSymbolAddress((void**)&ak,   g_ak);
    cudaGetSymbolAddress((void**)&av,   g_av);
    cudaGetSymbolAddress((void**)&wqkv, g_wqkv);
    cudaGetSymbolAddress((void**)&wo,   g_wo);

    int actTotal = L_SEQ * EMB;
    int wTotal   = 3 * EMB * EMB;
    int woTotal  = EMB * EMB;

    // 1. input / weight splits
    split_hlh<<<(actTotal + 255) / 256, 256>>>(query, aq, actTotal);
    split_hlh<<<(actTotal + 255) / 256, 256>>>(key,   ak, actTotal);
    split_hlh<<<(actTotal + 255) / 256, 256>>>(value, av, actTotal);
    split_hhl<<<(wTotal  + 255) / 256, 256>>>(w_in,  wqkv, wTotal);
    split_hhl<<<(woTotal + 255) / 256, 256>>>(w_out, wo,   woTotal);

    // 2. QKV projection — fused split epilogues (q->g_sq hlh, k->g_sk hhl, v fp32)
    dim3 qkv_grid(L_SEQ / 128, 12);
    gemm_qkv_kernel<<<qkv_grid, 256>>>(b_in);

    // 3. edge-type score LUT (from split q)
    type_scores_kernel<<<(NHEAD * L_SEQ) / 8, 256>>>(embK);

    // 4. V transpose + split
    dim3 vt_grid(L_SEQ / 64, NHEAD);
    v_split_transpose<<<vt_grid, 256>>>();

    // 5. flash attention (2-way j-split), writes split ctx directly
    cudaFuncSetAttribute(attn_mma_kernel, cudaFuncAttributeMaxDynamicSharedMemorySize,
                         ATTN_SMEM);
    dim3 attn_grid(L_SEQ / 64, NHEAD);
    attn_mma_kernel<<<attn_grid, 256, ATTN_SMEM>>>(eid);

    // 6. out projection
    dim3 out_grid(L_SEQ / 128, 4);
    gemm_out_kernel<<<out_grid, 256>>>(b_out, out);
}

// round 6
// speedup vs baseline: 1.5945x; 1.0378x over previous
#include <cuda_runtime.h>
#include <cuda_bf16.h>
#include <cstdint>

#define L_SEQ 2048
#define EMB   512
#define NHEAD 8
#define HDIM  64
#define NTYPE 10
#define KSPLIT 1536      // 3 * EMB  (activations [hi|lo|hi], weights [hi|hi|lo])

// ---------------------------------------------------------------------------
// Scratch (allocation-free rule: device globals)
// ---------------------------------------------------------------------------
__device__ float g_v[L_SEQ * EMB];
__device__ float g_ts[NHEAD * L_SEQ * 16];

__device__ __nv_bfloat16 g_aq[L_SEQ * KSPLIT];   // split input query
__device__ __nv_bfloat16 g_ak[L_SEQ * KSPLIT];   // split input key
__device__ __nv_bfloat16 g_av[L_SEQ * KSPLIT];   // split input value
__device__ __nv_bfloat16 g_wqkv[3 * EMB * KSPLIT];
__device__ __nv_bfloat16 g_wo[EMB * KSPLIT];     // k-cols PAIR-PERMUTED
__device__ __nv_bfloat16 g_sq[L_SEQ * KSPLIT];   // projected q, hlh, pair-permuted
__device__ __nv_bfloat16 g_sk[L_SEQ * KSPLIT];   // projected k, hhl, pair-permuted
__device__ __nv_bfloat16 g_actx[L_SEQ * KSPLIT]; // ctx, hlh, pair-permuted
__device__ __nv_bfloat16 g_svt[NHEAD * 2 * HDIM * L_SEQ];  // [h][vh|vl][j] j-pair-permuted

// pair permutation within a 16-element group: pair p -> position (p&3)*2 + (p>>2)
__device__ __forceinline__ int permute_paircol(int col) {   // col even
    int p = (col >> 1) & 7;
    return (col & ~15) + (((p & 3) * 2 + (p >> 2)) << 1);
}

// ---------------------------------------------------------------------------
// helpers
// ---------------------------------------------------------------------------
__device__ __forceinline__ uint32_t packbf(float lo, float hi) {
    uint32_t r;
    asm("cvt.rn.bf16x2.f32 %0, %1, %2;" : "=r"(r) : "f"(hi), "f"(lo));
    return r;
}
__device__ __forceinline__ uint32_t smem_to_u32(const void* p) {
    uint32_t a;
    asm("{ .reg .u64 t; cvta.to.shared.u64 t, %1; cvt.u32.u64 %0, t; }"
        : "=r"(a) : "l"(p));
    return a;
}
__device__ __forceinline__ void mma16816(float* d, const uint32_t* a,
                                         uint32_t b0, uint32_t b1) {
    asm volatile(
        "mma.sync.aligned.m16n8k16.row.col.f32.bf16.bf16.f32 "
        "{%0,%1,%2,%3}, {%4,%5,%6,%7}, {%8,%9}, {%0,%1,%2,%3};"
        : "+f"(d[0]), "+f"(d[1]), "+f"(d[2]), "+f"(d[3])
        : "r"(a[0]), "r"(a[1]), "r"(a[2]), "r"(a[3]), "r"(b0), "r"(b1));
}
__device__ __forceinline__ void cp16(uint32_t s, const void* g) {
    asm volatile("cp.async.cg.shared.global [%0], [%1], 16;"
                 :: "r"(s), "l"(g) : "memory");
}
#define CP_COMMIT asm volatile("cp.async.commit_group;" ::: "memory")

__device__ __forceinline__ void store_split(__nv_bfloat16* d, float v0, float v1,
                                            int mode) {
    float h0 = __bfloat162float(__float2bfloat16(v0));
    float h1 = __bfloat162float(__float2bfloat16(v1));
    uint32_t hh = packbf(h0, h1), ll = packbf(v0 - h0, v1 - h1);
    *(uint32_t*)d          = hh;
    *(uint32_t*)(d + 512)  = (mode == 1) ? ll : hh;
    *(uint32_t*)(d + 1024) = (mode == 1) ? hh : ll;
}

// ---------------------------------------------------------------------------
// input/weight splits
// ---------------------------------------------------------------------------
__global__ __launch_bounds__(256) void split_hlh(const float* __restrict__ x,
                                                 __nv_bfloat16* __restrict__ y,
                                                 int total) {
    int idx = blockIdx.x * 256 + threadIdx.x;
    if (idx >= total) return;
    int r = idx >> 9, c = idx & 511;
    float v = x[idx];
    __nv_bfloat16 h = __float2bfloat16(v);
    __nv_bfloat16 l = __float2bfloat16(v - __bfloat162float(h));
    __nv_bfloat16* yr = y + (size_t)r * KSPLIT;
    yr[c] = h; yr[512 + c] = l; yr[1024 + c] = h;
}
__global__ __launch_bounds__(256) void split_hhl(const float* __restrict__ x,
                                                 __nv_bfloat16* __restrict__ y,
                                                 int total) {
    int idx = blockIdx.x * 256 + threadIdx.x;
    if (idx >= total) return;
    int r = idx >> 9, c = idx & 511;
    float v = x[idx];
    __nv_bfloat16 h = __float2bfloat16(v);
    __nv_bfloat16 l = __float2bfloat16(v - __bfloat162float(h));
    __nv_bfloat16* yr = y + (size_t)r * KSPLIT;
    yr[c] = h; yr[512 + c] = h; yr[1024 + c] = l;
}
// w_out variant with k-column pair permutation (matches permuted g_actx)
__global__ __launch_bounds__(256) void split_hhl_perm(const float* __restrict__ x,
                                                      __nv_bfloat16* __restrict__ y,
                                                      int total) {
    int idx = blockIdx.x * 256 + threadIdx.x;
    if (idx >= total) return;
    int r = idx >> 9, c = idx & 511;
    float v = x[idx];
    __nv_bfloat16 h = __float2bfloat16(v);
    __nv_bfloat16 l = __float2bfloat16(v - __bfloat162float(h));
    int cp_ = permute_paircol(c & ~1) + (c & 1);
    __nv_bfloat16* yr = y + (size_t)r * KSPLIT;
    yr[cp_] = h; yr[512 + cp_] = h; yr[1024 + cp_] = l;
}

// ---------------------------------------------------------------------------
// V split + transpose -> g_svt, j-pairs permuted within 16-j groups
// ---------------------------------------------------------------------------
__global__ __launch_bounds__(256) void v_split_transpose() {
    __shared__ float tile[64][68];
    int h = blockIdx.y, j0 = blockIdx.x * 64;
    int tid = threadIdx.x;
    {
        int row = tid >> 2, cg = (tid & 3) * 16;
        const float* src = g_v + (size_t)(j0 + row) * EMB + h * HDIM + cg;
        #pragma unroll
        for (int i = 0; i < 4; i++)
            *(float4*)&tile[row][cg + i * 4] = *(const float4*)(src + i * 4);
    }
    __syncthreads();
    int d = tid >> 2, jg = (tid & 3) * 16;
    uint32_t hw[8], lw[8];
    #pragma unroll
    for (int p = 0; p < 8; p++) {
        float v0 = tile[jg + 2 * p][d], v1 = tile[jg + 2 * p + 1][d];
        float h0 = __bfloat162float(__float2bfloat16(v0));
        float h1 = __bfloat162float(__float2bfloat16(v1));
        hw[p] = packbf(h0, h1);
        lw[p] = packbf(v0 - h0, v1 - h1);
    }
    __nv_bfloat16* dsth = g_svt + ((size_t)(h * 128 + d) * L_SEQ + j0 + jg);
    __nv_bfloat16* dstl = g_svt + ((size_t)(h * 128 + 64 + d) * L_SEQ + j0 + jg);
    // permuted pair order: pos k holds pair inv(k) = {0,4,1,5,2,6,3,7}
    *(uint4*)dsth       = make_uint4(hw[0], hw[4], hw[1], hw[5]);
    *(uint4*)(dsth + 8) = make_uint4(hw[2], hw[6], hw[3], hw[7]);
    *(uint4*)dstl       = make_uint4(lw[0], lw[4], lw[1], lw[5]);
    *(uint4*)(dstl + 8) = make_uint4(lw[2], lw[6], lw[3], lw[7]);
}

// ---------------------------------------------------------------------------
// mma.sync GEMM, cp.async double-buffered (unchanged core).
// mode 0: fp32 out; mode 1: hlh split bf16 (permuted); mode 2: hhl (permuted)
// ---------------------------------------------------------------------------
__device__ __forceinline__ void gemm_core(const __nv_bfloat16* __restrict__ A,
                                          const __nv_bfloat16* __restrict__ B,
                                          const float* __restrict__ bias,
                                          float* __restrict__ Cf,
                                          __nv_bfloat16* __restrict__ Cs,
                                          int cn0, int m0, float scale, int mode) {
    __shared__ __nv_bfloat16 As[2][128 * 40];
    __shared__ __nv_bfloat16 Bs[2][128 * 40];
    int tid = threadIdx.x, wid = tid >> 5, lane = tid & 31;
    int gid = lane >> 2, qt = lane & 3;
    int wm = wid >> 2, wn = wid & 3;

    float acc[4][4][4] = {};
    int lrow = tid >> 1, lcol = (tid & 1) * 16;
    const __nv_bfloat16* Ap = A + (size_t)(m0 + lrow) * KSPLIT + lcol;
    const __nv_bfloat16* Bp = B + (size_t)lrow * KSPLIT + lcol;
    uint32_t sA[2] = {smem_to_u32(&As[0][lrow * 40 + lcol]),
                      smem_to_u32(&As[1][lrow * 40 + lcol])};
    uint32_t sB[2] = {smem_to_u32(&Bs[0][lrow * 40 + lcol]),
                      smem_to_u32(&Bs[1][lrow * 40 + lcol])};

    cp16(sA[0], Ap); cp16(sA[0] + 16, Ap + 8);
    cp16(sB[0], Bp); cp16(sB[0] + 16, Bp + 8);
    CP_COMMIT;

    for (int kt = 0; kt < KSPLIT / 32; kt++) {
        int cur = kt & 1;
        if (kt + 1 < KSPLIT / 32) {
            int nx = cur ^ 1;
            const __nv_bfloat16* a = Ap + (kt + 1) * 32;
            const __nv_bfloat16* b = Bp + (kt + 1) * 32;
            cp16(sA[nx], a); cp16(sA[nx] + 16, a + 8);
            cp16(sB[nx], b); cp16(sB[nx] + 16, b + 8);
            CP_COMMIT;
            asm volatile("cp.async.wait_group 1;" ::: "memory");
        } else {
            asm volatile("cp.async.wait_group 0;" ::: "memory");
        }
        __syncthreads();
        #pragma unroll
        for (int kc = 0; kc < 2; kc++) {
            uint32_t a[4][4];
            #pragma unroll
            for (int mf = 0; mf < 4; mf++) {
                int r = wm * 64 + mf * 16 + gid;
                int c = kc * 16 + qt * 2;
                a[mf][0] = *(const uint32_t*)&As[cur][r * 40 + c];
                a[mf][1] = *(const uint32_t*)&As[cur][(r + 8) * 40 + c];
                a[mf][2] = *(const uint32_t*)&As[cur][r * 40 + c + 8];
                a[mf][3] = *(const uint32_t*)&As[cur][(r + 8) * 40 + c + 8];
            }
            #pragma unroll
            for (int nf = 0; nf < 4; nf++) {
                int n = wn * 32 + nf * 8 + gid;
                int c = kc * 16 + qt * 2;
                uint32_t b0 = *(const uint32_t*)&Bs[cur][n * 40 + c];
                uint32_t b1 = *(const uint32_t*)&Bs[cur][n * 40 + c + 8];
                #pragma unroll
                for (int mf = 0; mf < 4; mf++)
                    mma16816(acc[mf][nf], a[mf], b0, b1);
            }
        }
        __syncthreads();
    }
    #pragma unroll
    for (int mf = 0; mf < 4; mf++) {
        int r = m0 + wm * 64 + mf * 16 + gid;
        #pragma unroll
        for (int nf = 0; nf < 4; nf++) {
            int cb = wn * 32 + nf * 8 + qt * 2;
            float b0 = __ldg(bias + cb), b1 = __ldg(bias + cb + 1);
            float v00 = scale * (acc[mf][nf][0] + b0);
            float v01 = scale * (acc[mf][nf][1] + b1);
            float v10 = scale * (acc[mf][nf][2] + b0);
            float v11 = scale * (acc[mf][nf][3] + b1);
            int col = cn0 + cb;
            if (mode == 0) {
                *(float2*)&Cf[(size_t)r * EMB + col]       = make_float2(v00, v01);
                *(float2*)&Cf[(size_t)(r + 8) * EMB + col] = make_float2(v10, v11);
            } else {
                int colp = permute_paircol(col);
                store_split(Cs + (size_t)r * KSPLIT + colp, v00, v01, mode);
                store_split(Cs + (size_t)(r + 8) * KSPLIT + colp, v10, v11, mode);
            }
        }
    }
}

__global__ __launch_bounds__(256) void gemm_qkv_kernel(const float* __restrict__ bias) {
    int m0 = blockIdx.x * 128;
    int nt = blockIdx.y;          // 0..11
    int sect = nt >> 2;
    int cn0 = (nt & 3) * 128;
    const __nv_bfloat16* Bw = g_wqkv + (size_t)nt * 128 * KSPLIT;
    if (sect == 0)
        gemm_core(g_aq, Bw, bias + nt * 128, nullptr, g_sq, cn0, m0, 0.125f, 1);
    else if (sect == 1)
        gemm_core(g_ak, Bw, bias + nt * 128, nullptr, g_sk, cn0, m0, 1.0f, 2);
    else
        gemm_core(g_av, Bw, bias + nt * 128, g_v, nullptr, cn0, m0, 1.0f, 0);
}
__global__ __launch_bounds__(256) void gemm_out_kernel(const float* __restrict__ bias,
                                                       float* __restrict__ C) {
    gemm_core(g_actx, g_wo + (size_t)blockIdx.y * 128 * KSPLIT,
              bias + blockIdx.y * 128, C, nullptr, blockIdx.y * 128,
              blockIdx.x * 128, 1.0f, 0);
}

// ---------------------------------------------------------------------------
// type_scores — reads permuted g_sq pairs
// ---------------------------------------------------------------------------
__global__ __launch_bounds__(256) void type_scores_kernel(
    const float* __restrict__ edge_embs) {
    __shared__ float emb[NTYPE * HDIM];
    int tid = threadIdx.x;
    for (int i = tid; i < NTYPE * HDIM; i += 256) emb[i] = edge_embs[i];
    __syncthreads();
    int warp = blockIdx.x * 8 + (tid >> 5);
    int lane = tid & 31;
    int h = warp >> 11, i = warp & (L_SEQ - 1);
    int pw = lane & 7;
    int colp = (lane >> 3) * 16 + ((pw & 3) * 2 + (pw >> 2)) * 2;  // permuted offset
    const __nv_bfloat16* qr = g_sq + (size_t)i * KSPLIT + h * HDIM + colp;
    float2 qh = __bfloat1622float2(*(const __nv_bfloat162*)qr);
    float2 ql = __bfloat1622float2(*(const __nv_bfloat162*)(qr + 512));
    float2 qv = make_float2(qh.x + ql.x, qh.y + ql.y);   // original cols lane*2, +1
    float s[NTYPE];
    #pragma unroll
    for (int t = 0; t < NTYPE; t++) {
        float2 e = *(const float2*)(emb + t * HDIM + lane * 2);
        s[t] = qv.x * e.x + qv.y * e.y;
    }
    #pragma unroll
    for (int off = 16; off > 0; off >>= 1)
        #pragma unroll
        for (int t = 0; t < NTYPE; t++)
            s[t] += __shfl_xor_sync(0xffffffffu, s[t], off);
    if (lane == 0) {
        float* dst = g_ts + (size_t)warp * 16;
        #pragma unroll
        for (int t = 0; t < NTYPE; t++) dst[t] = s[t];
    }
}

// ---------------------------------------------------------------------------
// Flash attention: i-tile 128, 8 warps, cp.async double-buffered K/V,
// hoisted Q fragments, LDS.64 conflict-free fragment loads.
// smem (bytes): Qs 0..36864 (pitch 288B), K 2x18432 @36864, V 2x20480 @73728,
//               Ts 8192 @114688.  total 122880.
// ---------------------------------------------------------------------------
#define QPITCH 144   // bf16
#define VPITCH 80    // bf16
#define SM_K 36864
#define SM_V 73728
#define SM_T 114688
#define ATTN_SMEM 122880

__global__ __launch_bounds__(256) void attn_mma_kernel(const int* __restrict__ edge_id) {
    extern __shared__ char smb[];
    __nv_bfloat16* Qs = (__nv_bfloat16*)smb;
    float* Ts = (float*)(smb + SM_T);
    uint32_t sbase = smem_to_u32(smb);

    int h = blockIdx.y;
    int i0 = blockIdx.x * 128;
    int tid = threadIdx.x, wid = tid >> 5, lane = tid & 31;
    int gid = lane >> 2, qt = lane & 3;

    // K/V tile loader (cp.async, 8x16B per thread)
    auto load_kv = [&](int j0, int buf) {
        int row = tid >> 2, q4 = tid & 3;
        {   // K: 64 rows x [kh(64)|kl(64)]
            int half = q4 >> 1, part = q4 & 1;
            const __nv_bfloat16* src = g_sk + (size_t)(j0 + row) * KSPLIT
                                       + half * 1024 + h * HDIM + part * 32;
            uint32_t dst = sbase + SM_K + buf * 18432 + row * 288 + half * 128 + part * 64;
            #pragma unroll
            for (int i = 0; i < 4; i++) cp16(dst + i * 16, src + i * 8);
        }
        {   // V: 128 d-rows x 64 j
            int vrow = tid >> 1, part = tid & 1;
            const __nv_bfloat16* src = g_svt + (size_t)(h * 128 + vrow) * L_SEQ
                                       + j0 + part * 32;
            uint32_t dst = sbase + SM_V + buf * 20480 + vrow * 160 + part * 64;
            #pragma unroll
            for (int i = 0; i < 4; i++) cp16(dst + i * 16, src + i * 8);
        }
    };

    // Q tile (cp.async, group 0) + Ts
    {
        int row = tid >> 1, half = tid & 1;
        const __nv_bfloat16* src = g_sq + (size_t)(i0 + row) * KSPLIT
                                   + half * 512 + h * HDIM;
        uint32_t dst = sbase + row * 288 + half * 128;
        #pragma unroll
        for (int i = 0; i < 8; i++) cp16(dst + i * 16, src + i * 8);
        const float* tsrc = g_ts + ((size_t)h * L_SEQ + i0 + row) * 16 + half * 8;
        *(float4*)(Ts + row * 16 + half * 8)     = *(const float4*)tsrc;
        *(float4*)(Ts + row * 16 + half * 8 + 4) = *(const float4*)(tsrc + 4);
    }
    CP_COMMIT;
    load_kv(0, 0);
    CP_COMMIT;
    asm volatile("cp.async.wait_group 1;" ::: "memory");
    __syncthreads();

    // hoist Q fragments (loop-invariant)
    int r0 = wid * 16 + gid;                   // 0..127
    uint32_t qh[4][4], ql[4][4];
    #pragma unroll
    for (int kc = 0; kc < 4; kc++) {
        uint2 lo = *(const uint2*)&Qs[r0 * QPITCH + kc * 16 + qt * 4];
        uint2 hi = *(const uint2*)&Qs[(r0 + 8) * QPITCH + kc * 16 + qt * 4];
        qh[kc][0] = lo.x; qh[kc][1] = hi.x; qh[kc][2] = lo.y; qh[kc][3] = hi.y;
        uint2 lo2 = *(const uint2*)&Qs[r0 * QPITCH + 64 + kc * 16 + qt * 4];
        uint2 hi2 = *(const uint2*)&Qs[(r0 + 8) * QPITCH + 64 + kc * 16 + qt * 4];
        ql[kc][0] = lo2.x; ql[kc][1] = hi2.x; ql[kc][2] = lo2.y; ql[kc][3] = hi2.y;
    }

    float o[8][4] = {};
    float rm0 = -1e30f, rm1 = -1e30f, rl0 = 0.f, rl1 = 0.f;
    const float* T0 = Ts + r0 * 16;
    const float* T1 = T0 + 128;

    for (int t = 0; t < 32; t++) {
        int cur = t & 1;
        if (t + 1 < 32) {
            load_kv((t + 1) * 64, cur ^ 1);
            CP_COMMIT;
            asm volatile("cp.async.wait_group 1;" ::: "memory");
        } else {
            asm volatile("cp.async.wait_group 0;" ::: "memory");
        }
        __syncthreads();
        const __nv_bfloat16* Ks = (const __nv_bfloat16*)(smb + SM_K + cur * 18432);
        const __nv_bfloat16* Vt = (const __nv_bfloat16*)(smb + SM_V + cur * 20480);
        int j0 = t * 64;

        // ---- S = qh·kh + ql·kh + qh·kl ----
        float sa[8][4] = {};
        #pragma unroll
        for (int kc = 0; kc < 4; kc++) {
            #pragma unroll
            for (int nt = 0; nt < 8; nt++) {
                int brow = nt * 8 + gid;
                uint2 kh = *(const uint2*)&Ks[brow * QPITCH + kc * 16 + qt * 4];
                uint2 kl = *(const uint2*)&Ks[brow * QPITCH + 64 + kc * 16 + qt * 4];
                mma16816(sa[nt], qh[kc], kh.x, kh.y);
                mma16816(sa[nt], ql[kc], kh.x, kh.y);
                mma16816(sa[nt], qh[kc], kl.x, kl.y);
            }
        }

        // ---- edge bias ----
        int grow0 = i0 + r0, grow1 = grow0 + 8;
        #pragma unroll
        for (int nt = 0; nt < 8; nt++) {
            int col = j0 + nt * 8 + qt * 2;
            int2 e0 = *(const int2*)&edge_id[(size_t)grow0 * L_SEQ + col];
            int2 e1 = *(const int2*)&edge_id[(size_t)grow1 * L_SEQ + col];
            sa[nt][0] += T0[e0.x]; sa[nt][1] += T0[e0.y];
            sa[nt][2] += T1[e1.x]; sa[nt][3] += T1[e1.y];
        }

        // ---- online softmax ----
        float mx0 = -1e30f, mx1 = -1e30f;
        #pragma unroll
        for (int nt = 0; nt < 8; nt++) {
            mx0 = fmaxf(mx0, fmaxf(sa[nt][0], sa[nt][1]));
            mx1 = fmaxf(mx1, fmaxf(sa[nt][2], sa[nt][3]));
        }
        mx0 = fmaxf(mx0, __shfl_xor_sync(0xffffffffu, mx0, 1));
        mx0 = fmaxf(mx0, __shfl_xor_sync(0xffffffffu, mx0, 2));
        mx1 = fmaxf(mx1, __shfl_xor_sync(0xffffffffu, mx1, 1));
        mx1 = fmaxf(mx1, __shfl_xor_sync(0xffffffffu, mx1, 2));
        float mn0 = fmaxf(rm0, mx0), mn1 = fmaxf(rm1, mx1);
        float c0 = __expf(rm0 - mn0), c1 = __expf(rm1 - mn1);
        float rs0 = 0.f, rs1 = 0.f;
        #pragma unroll
        for (int nt = 0; nt < 8; nt++) {
            sa[nt][0] = __expf(sa[nt][0] - mn0);
            sa[nt][1] = __expf(sa[nt][1] - mn0);
            sa[nt][2] = __expf(sa[nt][2] - mn1);
            sa[nt][3] = __expf(sa[nt][3] - mn1);
            rs0 += sa[nt][0] + sa[nt][1];
            rs1 += sa[nt][2] + sa[nt][3];
        }
        rs0 += __shfl_xor_sync(0xffffffffu, rs0, 1);
        rs0 += __shfl_xor_sync(0xffffffffu, rs0, 2);
        rs1 += __shfl_xor_sync(0xffffffffu, rs1, 1);
        rs1 += __shfl_xor_sync(0xffffffffu, rs1, 2);
        rl0 = rl0 * c0 + rs0; rl1 = rl1 * c1 + rs1;
        rm0 = mn0; rm1 = mn1;
        #pragma unroll
        for (int dt = 0; dt < 8; dt++) {
            o[dt][0] *= c0; o[dt][1] *= c0;
            o[dt][2] *= c1; o[dt][3] *= c1;
        }

        // ---- PV: O += ph·vh + pl·vh + ph·vl ----
        #pragma unroll
        for (int kc = 0; kc < 4; kc++) {
            const float* t0v = sa[2 * kc];
            const float* t1v = sa[2 * kc + 1];
            float h00 = __bfloat162float(__float2bfloat16(t0v[0]));
            float h01 = __bfloat162float(__float2bfloat16(t0v[1]));
            float h02 = __bfloat162float(__float2bfloat16(t0v[2]));
            float h03 = __bfloat162float(__float2bfloat16(t0v[3]));
            float h10 = __bfloat162float(__float2bfloat16(t1v[0]));
            float h11 = __bfloat162float(__float2bfloat16(t1v[1]));
            float h12 = __bfloat162float(__float2bfloat16(t1v[2]));
            float h13 = __bfloat162float(__float2bfloat16(t1v[3]));
            uint32_t ph[4], pl[4];
            ph[0] = packbf(h00, h01); ph[1] = packbf(h02, h03);
            ph[2] = packbf(h10, h11); ph[3] = packbf(h12, h13);
            pl[0] = packbf(t0v[0] - h00, t0v[1] - h01);
            pl[1] = packbf(t0v[2] - h02, t0v[3] - h03);
            pl[2] = packbf(t1v[0] - h10, t1v[1] - h11);
            pl[3] = packbf(t1v[2] - h12, t1v[3] - h13);
            #pragma unroll
            for (int dt = 0; dt < 8; dt++) {
                int vrh = dt * 8 + gid;
                uint2 vh = *(const uint2*)&Vt[vrh * VPITCH + kc * 16 + qt * 4];
                uint2 vl = *(const uint2*)&Vt[(64 + vrh) * VPITCH + kc * 16 + qt * 4];
                mma16816(o[dt], ph, vh.x, vh.y);
                mma16816(o[dt], pl, vh.x, vh.y);
                mma16816(o[dt], ph, vl.x, vl.y);
            }
        }
        __syncthreads();
    }

    // ---- normalize + permuted hlh-split ctx store ----
    float inv0 = 1.0f / rl0, inv1 = 1.0f / rl1;
    __nv_bfloat16* dst0 = g_actx + (size_t)(i0 + r0) * KSPLIT + h * HDIM;
    __nv_bfloat16* dst1 = g_actx + (size_t)(i0 + r0 + 8) * KSPLIT + h * HDIM;
    #pragma unroll
    for (int dt = 0; dt < 8; dt++) {
        int c = dt * 8 + qt * 2;
        int cp_ = permute_paircol(c);
        store_split(dst0 + cp_, o[dt][0] * inv0, o[dt][1] * inv0, 1);
        store_split(dst1 + cp_, o[dt][2] * inv1, o[dt][3] * inv1, 1);
    }
}

// ---------------------------------------------------------------------------
extern "C" void kernel_launch(void* const* d_in, const int* in_sizes, int n_in,
                              void* d_out, int out_size)
{
    const float* query = (const float*)d_in[0];
    const float* key   = (const float*)d_in[1];
    const float* value = (const float*)d_in[2];
    const int*   eid   = (const int*)d_in[3];
    const float* w_in  = (const float*)d_in[4];
    const float* b_in  = (const float*)d_in[5];
    const float* w_out = (const float*)d_in[6];
    const float* b_out = (const float*)d_in[7];
    const float* embK  = (const float*)d_in[8];
    float* out = (float*)d_out;

    __nv_bfloat16 *aq, *ak, *av, *wqkv, *wo;
    cudaGetSymbolAddress((void**)&aq,   g_aq);
    cudaGetSymbolAddress((void**)&ak,   g_ak);
    cudaGetSymbolAddress((void**)&av,   g_av);
    cudaGetSymbolAddress((void**)&wqkv, g_wqkv);
    cudaGetSymbolAddress((void**)&wo,   g_wo);

    int actTotal = L_SEQ * EMB;
    int wTotal   = 3 * EMB * EMB;
    int woTotal  = EMB * EMB;

    // 1. input / weight splits
    split_hlh<<<(actTotal + 255) / 256, 256>>>(query, aq, actTotal);
    split_hlh<<<(actTotal + 255) / 256, 256>>>(key,   ak, actTotal);
    split_hlh<<<(actTotal + 255) / 256, 256>>>(value, av, actTotal);
    split_hhl<<<(wTotal  + 255) / 256, 256>>>(w_in,  wqkv, wTotal);
    split_hhl_perm<<<(woTotal + 255) / 256, 256>>>(w_out, wo, woTotal);

    // 2. QKV projection — fused split epilogues (permuted q/k, v fp32)
    dim3 qkv_grid(L_SEQ / 128, 12);
    gemm_qkv_kernel<<<qkv_grid, 256>>>(b_in);

    // 3. edge-type score LUT
    type_scores_kernel<<<(NHEAD * L_SEQ) / 8, 256>>>(embK);

    // 4. V transpose + split (permuted)
    dim3 vt_grid(L_SEQ / 64, NHEAD);
    v_split_transpose<<<vt_grid, 256>>>();

    // 5. flash attention (128-row i-tiles, single wave)
    cudaFuncSetAttribute(attn_mma_kernel, cudaFuncAttributeMaxDynamicSharedMemorySize,
                         ATTN_SMEM);
    dim3 attn_grid(L_SEQ / 128, NHEAD);
    attn_mma_kernel<<<attn_grid, 256, ATTN_SMEM>>>(eid);

    // 6. out projection (permuted k on both sides — dot product invariant)
    dim3 out_grid(L_SEQ / 128, 4);
    gemm_out_kernel<<<out_grid, 256>>>(b_out, out);
}

// round 7
// speedup vs baseline: 1.7046x; 1.0690x over previous
#include <cuda_runtime.h>
#include <cuda_fp16.h>
#include <cstdint>

#define L_SEQ 2048
#define EMB   512
#define NHEAD 8
#define HDIM  64
#define NTYPE 10
#define KSPLIT 1536      // 3 * EMB  (activations [hi|lo|hi], weights [hi|hi|lo])

// ---------------------------------------------------------------------------
// Scratch (allocation-free rule: device globals)
// ---------------------------------------------------------------------------
__device__ float g_v[L_SEQ * EMB];
__device__ float g_ts[NHEAD * L_SEQ * 16];

__device__ __half g_aq[L_SEQ * KSPLIT];   // split input query
__device__ __half g_ak[L_SEQ * KSPLIT];   // split input key
__device__ __half g_av[L_SEQ * KSPLIT];   // split input value
__device__ __half g_wqkv[3 * EMB * KSPLIT];
__device__ __half g_wo[EMB * KSPLIT];     // k-cols PAIR-PERMUTED
__device__ __half g_sq[L_SEQ * KSPLIT];   // projected q, hlh, pair-permuted
__device__ __half g_sk[L_SEQ * KSPLIT];   // projected k, hhl, pair-permuted
__device__ __half g_actx[L_SEQ * KSPLIT]; // ctx, hlh, pair-permuted
__device__ __half g_svt[NHEAD * 2 * HDIM * L_SEQ];  // [h][vh|vl][j] j-pair-permuted

// pair permutation within a 16-element group: pair p -> position (p&3)*2 + (p>>2)
__device__ __forceinline__ int permute_paircol(int col) {   // col even
    int p = (col >> 1) & 7;
    return (col & ~15) + (((p & 3) * 2 + (p >> 2)) << 1);
}

// ---------------------------------------------------------------------------
// helpers
// ---------------------------------------------------------------------------
__device__ __forceinline__ uint32_t packh(float lo, float hi) {
    uint32_t r;
    asm("cvt.rn.f16x2.f32 %0, %1, %2;" : "=r"(r) : "f"(hi), "f"(lo));
    return r;
}
__device__ __forceinline__ float2 unph(uint32_t u) {
    __half2 h = *reinterpret_cast<__half2*>(&u);
    return __half22float2(h);
}
__device__ __forceinline__ uint32_t smem_to_u32(const void* p) {
    uint32_t a;
    asm("{ .reg .u64 t; cvta.to.shared.u64 t, %1; cvt.u32.u64 %0, t; }"
        : "=r"(a) : "l"(p));
    return a;
}
// fp32-accumulate fp16 MMA (hi terms)
__device__ __forceinline__ void mma16816(float* d, const uint32_t* a,
                                         uint32_t b0, uint32_t b1) {
    asm volatile(
        "mma.sync.aligned.m16n8k16.row.col.f32.f16.f16.f32 "
        "{%0,%1,%2,%3}, {%4,%5,%6,%7}, {%8,%9}, {%0,%1,%2,%3};"
        : "+f"(d[0]), "+f"(d[1]), "+f"(d[2]), "+f"(d[3])
        : "r"(a[0]), "r"(a[1]), "r"(a[2]), "r"(a[3]), "r"(b0), "r"(b1));
}
// fp16-accumulate fp16 MMA (small correction terms, 2x rate expected)
__device__ __forceinline__ void mma16816h(uint32_t* c, const uint32_t* a,
                                          uint32_t b0, uint32_t b1) {
    asm volatile(
        "mma.sync.aligned.m16n8k16.row.col.f16.f16.f16.f16 "
        "{%0,%1}, {%2,%3,%4,%5}, {%6,%7}, {%0,%1};"
        : "+r"(c[0]), "+r"(c[1])
        : "r"(a[0]), "r"(a[1]), "r"(a[2]), "r"(a[3]), "r"(b0), "r"(b1));
}
__device__ __forceinline__ void cp16(uint32_t s, const void* g) {
    asm volatile("cp.async.cg.shared.global [%0], [%1], 16;"
                 :: "r"(s), "l"(g) : "memory");
}
#define CP_COMMIT asm volatile("cp.async.commit_group;" ::: "memory")

__device__ __forceinline__ void store_split(__half* d, float v0, float v1,
                                            int mode) {
    float h0 = __half2float(__float2half(v0));
    float h1 = __half2float(__float2half(v1));
    uint32_t hh = packh(h0, h1), ll = packh(v0 - h0, v1 - h1);
    *(uint32_t*)d          = hh;
    *(uint32_t*)(d + 512)  = (mode == 1) ? ll : hh;
    *(uint32_t*)(d + 1024) = (mode == 1) ? hh : ll;
}

// ---------------------------------------------------------------------------
// input/weight splits (fp16 digits)
// ---------------------------------------------------------------------------
__global__ __launch_bounds__(256) void split_hlh(const float* __restrict__ x,
                                                 __half* __restrict__ y,
                                                 int total) {
    int idx = blockIdx.x * 256 + threadIdx.x;
    if (idx >= total) return;
    int r = idx >> 9, c = idx & 511;
    float v = x[idx];
    __half h = __float2half(v);
    __half l = __float2half(v - __half2float(h));
    __half* yr = y + (size_t)r * KSPLIT;
    yr[c] = h; yr[512 + c] = l; yr[1024 + c] = h;
}
__global__ __launch_bounds__(256) void split_hhl(const float* __restrict__ x,
                                                 __half* __restrict__ y,
                                                 int total) {
    int idx = blockIdx.x * 256 + threadIdx.x;
    if (idx >= total) return;
    int r = idx >> 9, c = idx & 511;
    float v = x[idx];
    __half h = __float2half(v);
    __half l = __float2half(v - __half2float(h));
    __half* yr = y + (size_t)r * KSPLIT;
    yr[c] = h; yr[512 + c] = h; yr[1024 + c] = l;
}
__global__ __launch_bounds__(256) void split_hhl_perm(const float* __restrict__ x,
                                                      __half* __restrict__ y,
                                                      int total) {
    int idx = blockIdx.x * 256 + threadIdx.x;
    if (idx >= total) return;
    int r = idx >> 9, c = idx & 511;
    float v = x[idx];
    __half h = __float2half(v);
    __half l = __float2half(v - __half2float(h));
    int cp_ = permute_paircol(c & ~1) + (c & 1);
    __half* yr = y + (size_t)r * KSPLIT;
    yr[cp_] = h; yr[512 + cp_] = h; yr[1024 + cp_] = l;
}

// ---------------------------------------------------------------------------
// V split + transpose -> g_svt, j-pairs permuted within 16-j groups
// ---------------------------------------------------------------------------
__global__ __launch_bounds__(256) void v_split_transpose() {
    __shared__ float tile[64][68];
    int h = blockIdx.y, j0 = blockIdx.x * 64;
    int tid = threadIdx.x;
    {
        int row = tid >> 2, cg = (tid & 3) * 16;
        const float* src = g_v + (size_t)(j0 + row) * EMB + h * HDIM + cg;
        #pragma unroll
        for (int i = 0; i < 4; i++)
            *(float4*)&tile[row][cg + i * 4] = *(const float4*)(src + i * 4);
    }
    __syncthreads();
    int d = tid >> 2, jg = (tid & 3) * 16;
    uint32_t hw[8], lw[8];
    #pragma unroll
    for (int p = 0; p < 8; p++) {
        float v0 = tile[jg + 2 * p][d], v1 = tile[jg + 2 * p + 1][d];
        float h0 = __half2float(__float2half(v0));
        float h1 = __half2float(__float2half(v1));
        hw[p] = packh(h0, h1);
        lw[p] = packh(v0 - h0, v1 - h1);
    }
    __half* dsth = g_svt + ((size_t)(h * 128 + d) * L_SEQ + j0 + jg);
    __half* dstl = g_svt + ((size_t)(h * 128 + 64 + d) * L_SEQ + j0 + jg);
    *(uint4*)dsth       = make_uint4(hw[0], hw[4], hw[1], hw[5]);
    *(uint4*)(dsth + 8) = make_uint4(hw[2], hw[6], hw[3], hw[7]);
    *(uint4*)dstl       = make_uint4(lw[0], lw[4], lw[1], lw[5]);
    *(uint4*)(dstl + 8) = make_uint4(lw[2], lw[6], lw[3], lw[7]);
}

// ---------------------------------------------------------------------------
// mma.sync GEMM, cp.async double-buffered.
// kt 0-15 = hi*hi (fp32 acc); kt 16-47 = cross terms (fp16 acc, 2x rate).
// ---------------------------------------------------------------------------
__device__ __forceinline__ void gemm_core(const __half* __restrict__ A,
                                          const __half* __restrict__ B,
                                          const float* __restrict__ bias,
                                          float* __restrict__ Cf,
                                          __half* __restrict__ Cs,
                                          int cn0, int m0, float scale, int mode) {
    __shared__ __half As[2][128 * 40];
    __shared__ __half Bs[2][128 * 40];
    int tid = threadIdx.x, wid = tid >> 5, lane = tid & 31;
    int gid = lane >> 2, qt = lane & 3;
    int wm = wid >> 2, wn = wid & 3;

    float acc[4][4][4] = {};
    uint32_t acch[4][4][2] = {};
    int lrow = tid >> 1, lcol = (tid & 1) * 16;
    const __half* Ap = A + (size_t)(m0 + lrow) * KSPLIT + lcol;
    const __half* Bp = B + (size_t)lrow * KSPLIT + lcol;
    uint32_t sA[2] = {smem_to_u32(&As[0][lrow * 40 + lcol]),
                      smem_to_u32(&As[1][lrow * 40 + lcol])};
    uint32_t sB[2] = {smem_to_u32(&Bs[0][lrow * 40 + lcol]),
                      smem_to_u32(&Bs[1][lrow * 40 + lcol])};

    cp16(sA[0], Ap); cp16(sA[0] + 16, Ap + 8);
    cp16(sB[0], Bp); cp16(sB[0] + 16, Bp + 8);
    CP_COMMIT;

    for (int kt = 0; kt < KSPLIT / 32; kt++) {
        int cur = kt & 1;
        if (kt + 1 < KSPLIT / 32) {
            int nx = cur ^ 1;
            const __half* a = Ap + (kt + 1) * 32;
            const __half* b = Bp + (kt + 1) * 32;
            cp16(sA[nx], a); cp16(sA[nx] + 16, a + 8);
            cp16(sB[nx], b); cp16(sB[nx] + 16, b + 8);
            CP_COMMIT;
            asm volatile("cp.async.wait_group 1;" ::: "memory");
        } else {
            asm volatile("cp.async.wait_group 0;" ::: "memory");
        }
        __syncthreads();
        bool hi_term = (kt < 16);   // k < 512 : hi*hi
        #pragma unroll
        for (int kc = 0; kc < 2; kc++) {
            uint32_t a[4][4];
            #pragma unroll
            for (int mf = 0; mf < 4; mf++) {
                int r = wm * 64 + mf * 16 + gid;
                int c = kc * 16 + qt * 2;
                a[mf][0] = *(const uint32_t*)&As[cur][r * 40 + c];
                a[mf][1] = *(const uint32_t*)&As[cur][(r + 8) * 40 + c];
                a[mf][2] = *(const uint32_t*)&As[cur][r * 40 + c + 8];
                a[mf][3] = *(const uint32_t*)&As[cur][(r + 8) * 40 + c + 8];
            }
            #pragma unroll
            for (int nf = 0; nf < 4; nf++) {
                int n = wn * 32 + nf * 8 + gid;
                int c = kc * 16 + qt * 2;
                uint32_t b0 = *(const uint32_t*)&Bs[cur][n * 40 + c];
                uint32_t b1 = *(const uint32_t*)&Bs[cur][n * 40 + c + 8];
                if (hi_term) {
                    #pragma unroll
                    for (int mf = 0; mf < 4; mf++)
                        mma16816(acc[mf][nf], a[mf], b0, b1);
                } else {
                    #pragma unroll
                    for (int mf = 0; mf < 4; mf++)
                        mma16816h(acch[mf][nf], a[mf], b0, b1);
                }
            }
        }
        __syncthreads();
    }
    #pragma unroll
    for (int mf = 0; mf < 4; mf++) {
        int r = m0 + wm * 64 + mf * 16 + gid;
        #pragma unroll
        for (int nf = 0; nf < 4; nf++) {
            int cb = wn * 32 + nf * 8 + qt * 2;
            float b0 = __ldg(bias + cb), b1 = __ldg(bias + cb + 1);
            float2 c0 = unph(acch[mf][nf][0]);
            float2 c1 = unph(acch[mf][nf][1]);
            float v00 = scale * (acc[mf][nf][0] + c0.x + b0);
            float v01 = scale * (acc[mf][nf][1] + c0.y + b1);
            float v10 = scale * (acc[mf][nf][2] + c1.x + b0);
            float v11 = scale * (acc[mf][nf][3] + c1.y + b1);
            int col = cn0 + cb;
            if (mode == 0) {
                *(float2*)&Cf[(size_t)r * EMB + col]       = make_float2(v00, v01);
                *(float2*)&Cf[(size_t)(r + 8) * EMB + col] = make_float2(v10, v11);
            } else {
                int colp = permute_paircol(col);
                store_split(Cs + (size_t)r * KSPLIT + colp, v00, v01, mode);
                store_split(Cs + (size_t)(r + 8) * KSPLIT + colp, v10, v11, mode);
            }
        }
    }
}

__global__ __launch_bounds__(256) void gemm_qkv_kernel(const float* __restrict__ bias) {
    int m0 = blockIdx.x * 128;
    int nt = blockIdx.y;          // 0..11
    int sect = nt >> 2;
    int cn0 = (nt & 3) * 128;
    const __half* Bw = g_wqkv + (size_t)nt * 128 * KSPLIT;
    if (sect == 0)
        gemm_core(g_aq, Bw, bias + nt * 128, nullptr, g_sq, cn0, m0, 0.125f, 1);
    else if (sect == 1)
        gemm_core(g_ak, Bw, bias + nt * 128, nullptr, g_sk, cn0, m0, 1.0f, 2);
    else
        gemm_core(g_av, Bw, bias + nt * 128, g_v, nullptr, cn0, m0, 1.0f, 0);
}
__global__ __launch_bounds__(256) void gemm_out_kernel(const float* __restrict__ bias,
                                                       float* __restrict__ C) {
    gemm_core(g_actx, g_wo + (size_t)blockIdx.y * 128 * KSPLIT,
              bias + blockIdx.y * 128, C, nullptr, blockIdx.y * 128,
              blockIdx.x * 128, 1.0f, 0);
}

// ---------------------------------------------------------------------------
// type_scores — reads permuted g_sq pairs (fp16 hi+lo)
// ---------------------------------------------------------------------------
__global__ __launch_bounds__(256) void type_scores_kernel(
    const float* __restrict__ edge_embs) {
    __shared__ float emb[NTYPE * HDIM];
    int tid = threadIdx.x;
    for (int i = tid; i < NTYPE * HDIM; i += 256) emb[i] = edge_embs[i];
    __syncthreads();
    int warp = blockIdx.x * 8 + (tid >> 5);
    int lane = tid & 31;
    int h = warp >> 11, i = warp & (L_SEQ - 1);
    int pw = lane & 7;
    int colp = (lane >> 3) * 16 + ((pw & 3) * 2 + (pw >> 2)) * 2;
    const __half* qr = g_sq + (size_t)i * KSPLIT + h * HDIM + colp;
    float2 qh = __half22float2(*(const __half2*)qr);
    float2 ql = __half22float2(*(const __half2*)(qr + 512));
    float2 qv = make_float2(qh.x + ql.x, qh.y + ql.y);
    float s[NTYPE];
    #pragma unroll
    for (int t = 0; t < NTYPE; t++) {
        float2 e = *(const float2*)(emb + t * HDIM + lane * 2);
        s[t] = qv.x * e.x + qv.y * e.y;
    }
    #pragma unroll
    for (int off = 16; off > 0; off >>= 1)
        #pragma unroll
        for (int t = 0; t < NTYPE; t++)
            s[t] += __shfl_xor_sync(0xffffffffu, s[t], off);
    if (lane == 0) {
        float* dst = g_ts + (size_t)warp * 16;
        #pragma unroll
        for (int t = 0; t < NTYPE; t++) dst[t] = s[t];
    }
}

// ---------------------------------------------------------------------------
// Flash attention: i-tile 128, 8 warps, cp.async double-buffered K/V,
// hoisted Q frags; hi terms fp32-acc, cross terms fp16-acc.
// ---------------------------------------------------------------------------
#define QPITCH 144   // fp16
#define VPITCH 80
#define SM_K 36864
#define SM_V 73728
#define SM_T 114688
#define ATTN_SMEM 122880

__global__ __launch_bounds__(256) void attn_mma_kernel(const int* __restrict__ edge_id) {
    extern __shared__ char smb[];
    __half* Qs = (__half*)smb;
    float* Ts = (float*)(smb + SM_T);
    uint32_t sbase = smem_to_u32(smb);

    int h = blockIdx.y;
    int i0 = blockIdx.x * 128;
    int tid = threadIdx.x, wid = tid >> 5, lane = tid & 31;
    int gid = lane >> 2, qt = lane & 3;

    auto load_kv = [&](int j0, int buf) {
        int row = tid >> 2, q4 = tid & 3;
        {   // K: 64 rows x [kh(64)|kl(64)]  (hhl: kh@0, kl@1024)
            int half_ = q4 >> 1, part = q4 & 1;
            const __half* src = g_sk + (size_t)(j0 + row) * KSPLIT
                                + half_ * 1024 + h * HDIM + part * 32;
            uint32_t dst = sbase + SM_K + buf * 18432 + row * 288 + half_ * 128 + part * 64;
            #pragma unroll
            for (int i = 0; i < 4; i++) cp16(dst + i * 16, src + i * 8);
        }
        {   // V: 128 d-rows x 64 j
            int vrow = tid >> 1, part = tid & 1;
            const __half* src = g_svt + (size_t)(h * 128 + vrow) * L_SEQ
                                + j0 + part * 32;
            uint32_t dst = sbase + SM_V + buf * 20480 + vrow * 160 + part * 64;
            #pragma unroll
            for (int i = 0; i < 4; i++) cp16(dst + i * 16, src + i * 8);
        }
    };

    {   // Q tile + Ts
        int row = tid >> 1, half_ = tid & 1;
        const __half* src = g_sq + (size_t)(i0 + row) * KSPLIT
                            + half_ * 512 + h * HDIM;
        uint32_t dst = sbase + row * 288 + half_ * 128;
        #pragma unroll
        for (int i = 0; i < 8; i++) cp16(dst + i * 16, src + i * 8);
        const float* tsrc = g_ts + ((size_t)h * L_SEQ + i0 + row) * 16 + half_ * 8;
        *(float4*)(Ts + row * 16 + half_ * 8)     = *(const float4*)tsrc;
        *(float4*)(Ts + row * 16 + half_ * 8 + 4) = *(const float4*)(tsrc + 4);
    }
    CP_COMMIT;
    load_kv(0, 0);
    CP_COMMIT;
    asm volatile("cp.async.wait_group 1;" ::: "memory");
    __syncthreads();

    int r0 = wid * 16 + gid;
    uint32_t qh[4][4], ql[4][4];
    #pragma unroll
    for (int kc = 0; kc < 4; kc++) {
        uint2 lo = *(const uint2*)&Qs[r0 * QPITCH + kc * 16 + qt * 4];
        uint2 hi = *(const uint2*)&Qs[(r0 + 8) * QPITCH + kc * 16 + qt * 4];
        qh[kc][0] = lo.x; qh[kc][1] = hi.x; qh[kc][2] = lo.y; qh[kc][3] = hi.y;
        uint2 lo2 = *(const uint2*)&Qs[r0 * QPITCH + 64 + kc * 16 + qt * 4];
        uint2 hi2 = *(const uint2*)&Qs[(r0 + 8) * QPITCH + 64 + kc * 16 + qt * 4];
        ql[kc][0] = lo2.x; ql[kc][1] = hi2.x; ql[kc][2] = lo2.y; ql[kc][3] = hi2.y;
    }

    float o[8][4] = {};
    float rm0 = -1e30f, rm1 = -1e30f, rl0 = 0.f, rl1 = 0.f;
    const float* T0 = Ts + r0 * 16;
    const float* T1 = T0 + 128;

    for (int t = 0; t < 32; t++) {
        int cur = t & 1;
        if (t + 1 < 32) {
            load_kv((t + 1) * 64, cur ^ 1);
            CP_COMMIT;
            asm volatile("cp.async.wait_group 1;" ::: "memory");
        } else {
            asm volatile("cp.async.wait_group 0;" ::: "memory");
        }
        __syncthreads();
        const __half* Ks = (const __half*)(smb + SM_K + cur * 18432);
        const __half* Vt = (const __half*)(smb + SM_V + cur * 20480);
        int j0 = t * 64;

        // ---- S: hi fp32-acc, crosses fp16-acc ----
        float sa[8][4] = {};
        uint32_t sc[8][2] = {};
        #pragma unroll
        for (int kc = 0; kc < 4; kc++) {
            #pragma unroll
            for (int nt = 0; nt < 8; nt++) {
                int brow = nt * 8 + gid;
                uint2 kh = *(const uint2*)&Ks[brow * QPITCH + kc * 16 + qt * 4];
                uint2 kl = *(const uint2*)&Ks[brow * QPITCH + 64 + kc * 16 + qt * 4];
                mma16816(sa[nt], qh[kc], kh.x, kh.y);
                mma16816h(sc[nt], ql[kc], kh.x, kh.y);
                mma16816h(sc[nt], qh[kc], kl.x, kl.y);
            }
        }
        #pragma unroll
        for (int nt = 0; nt < 8; nt++) {
            float2 ca = unph(sc[nt][0]);
            float2 cb = unph(sc[nt][1]);
            sa[nt][0] += ca.x; sa[nt][1] += ca.y;
            sa[nt][2] += cb.x; sa[nt][3] += cb.y;
        }

        // ---- edge bias ----
        int grow0 = i0 + r0, grow1 = grow0 + 8;
        #pragma unroll
        for (int nt = 0; nt < 8; nt++) {
            int col = j0 + nt * 8 + qt * 2;
            int2 e0 = *(const int2*)&edge_id[(size_t)grow0 * L_SEQ + col];
            int2 e1 = *(const int2*)&edge_id[(size_t)grow1 * L_SEQ + col];
            sa[nt][0] += T0[e0.x]; sa[nt][1] += T0[e0.y];
            sa[nt][2] += T1[e1.x]; sa[nt][3] += T1[e1.y];
        }

        // ---- online softmax ----
        float mx0 = -1e30f, mx1 = -1e30f;
        #pragma unroll
        for (int nt = 0; nt < 8; nt++) {
            mx0 = fmaxf(mx0, fmaxf(sa[nt][0], sa[nt][1]));
            mx1 = fmaxf(mx1, fmaxf(sa[nt][2], sa[nt][3]));
        }
        mx0 = fmaxf(mx0, __shfl_xor_sync(0xffffffffu, mx0, 1));
        mx0 = fmaxf(mx0, __shfl_xor_sync(0xffffffffu, mx0, 2));
        mx1 = fmaxf(mx1, __shfl_xor_sync(0xffffffffu, mx1, 1));
        mx1 = fmaxf(mx1, __shfl_xor_sync(0xffffffffu, mx1, 2));
        float mn0 = fmaxf(rm0, mx0), mn1 = fmaxf(rm1, mx1);
        float c0 = __expf(rm0 - mn0), c1 = __expf(rm1 - mn1);
        float rs0 = 0.f, rs1 = 0.f;
        #pragma unroll
        for (int nt = 0; nt < 8; nt++) {
            sa[nt][0] = __expf(sa[nt][0] - mn0);
            sa[nt][1] = __expf(sa[nt][1] - mn0);
            sa[nt][2] = __expf(sa[nt][2] - mn1);
            sa[nt][3] = __expf(sa[nt][3] - mn1);
            rs0 += sa[nt][0] + sa[nt][1];
            rs1 += sa[nt][2] + sa[nt][3];
        }
        rs0 += __shfl_xor_sync(0xffffffffu, rs0, 1);
        rs0 += __shfl_xor_sync(0xffffffffu, rs0, 2);
        rs1 += __shfl_xor_sync(0xffffffffu, rs1, 1);
        rs1 += __shfl_xor_sync(0xffffffffu, rs1, 2);
        rl0 = rl0 * c0 + rs0; rl1 = rl1 * c1 + rs1;
        rm0 = mn0; rm1 = mn1;
        #pragma unroll
        for (int dt = 0; dt < 8; dt++) {
            o[dt][0] *= c0; o[dt][1] *= c0;
            o[dt][2] *= c1; o[dt][3] *= c1;
        }

        // ---- PV: hi fp32-acc, crosses fp16-acc (folded per tile) ----
        uint32_t oc[8][2] = {};
        #pragma unroll
        for (int kc = 0; kc < 4; kc++) {
            const float* t0v = sa[2 * kc];
            const float* t1v = sa[2 * kc + 1];
            float h00 = __half2float(__float2half(t0v[0]));
            float h01 = __half2float(__float2half(t0v[1]));
            float h02 = __half2float(__float2half(t0v[2]));
            float h03 = __half2float(__float2half(t0v[3]));
            float h10 = __half2float(__float2half(t1v[0]));
            float h11 = __half2float(__float2half(t1v[1]));
            float h12 = __half2float(__float2half(t1v[2]));
            float h13 = __half2float(__float2half(t1v[3]));
            uint32_t ph[4], pl[4];
            ph[0] = packh(h00, h01); ph[1] = packh(h02, h03);
            ph[2] = packh(h10, h11); ph[3] = packh(h12, h13);
            pl[0] = packh(t0v[0] - h00, t0v[1] - h01);
            pl[1] = packh(t0v[2] - h02, t0v[3] - h03);
            pl[2] = packh(t1v[0] - h10, t1v[1] - h11);
            pl[3] = packh(t1v[2] - h12, t1v[3] - h13);
            #pragma unroll
            for (int dt = 0; dt < 8; dt++) {
                int vrh = dt * 8 + gid;
                uint2 vh = *(const uint2*)&Vt[vrh * VPITCH + kc * 16 + qt * 4];
                uint2 vl = *(const uint2*)&Vt[(64 + vrh) * VPITCH + kc * 16 + qt * 4];
                mma16816(o[dt], ph, vh.x, vh.y);
                mma16816h(oc[dt], pl, vh.x, vh.y);
                mma16816h(oc[dt], ph, vl.x, vl.y);
            }
        }
        #pragma unroll
        for (int dt = 0; dt < 8; dt++) {
            float2 ca = unph(oc[dt][0]);
            float2 cb = unph(oc[dt][1]);
            o[dt][0] += ca.x; o[dt][1] += ca.y;
            o[dt][2] += cb.x; o[dt][3] += cb.y;
        }
        __syncthreads();
    }

    // ---- normalize + permuted hlh-split ctx store ----
    float inv0 = 1.0f / rl0, inv1 = 1.0f / rl1;
    __half* dst0 = g_actx + (size_t)(i0 + r0) * KSPLIT + h * HDIM;
    __half* dst1 = g_actx + (size_t)(i0 + r0 + 8) * KSPLIT + h * HDIM;
    #pragma unroll
    for (int dt = 0; dt < 8; dt++) {
        int c = dt * 8 + qt * 2;
        int cp_ = permute_paircol(c);
        store_split(dst0 + cp_, o[dt][0] * inv0, o[dt][1] * inv0, 1);
        store_split(dst1 + cp_, o[dt][2] * inv1, o[dt][3] * inv1, 1);
    }
}

// ---------------------------------------------------------------------------
extern "C" void kernel_launch(void* const* d_in, const int* in_sizes, int n_in,
                              void* d_out, int out_size)
{
    const float* query = (const float*)d_in[0];
    const float* key   = (const float*)d_in[1];
    const float* value = (const float*)d_in[2];
    const int*   eid   = (const int*)d_in[3];
    const float* w_in  = (const float*)d_in[4];
    const float* b_in  = (const float*)d_in[5];
    const float* w_out = (const float*)d_in[6];
    const float* b_out = (const float*)d_in[7];
    const float* embK  = (const float*)d_in[8];
    float* out = (float*)d_out;

    __half *aq, *ak, *av, *wqkv, *wo;
    cudaGetSymbolAddress((void**)&aq,   g_aq);
    cudaGetSymbolAddress((void**)&ak,   g_ak);
    cudaGetSymbolAddress((void**)&av,   g_av);
    cudaGetSymbolAddress((void**)&wqkv, g_wqkv);
    cudaGetSymbolAddress((void**)&wo,   g_wo);

    int actTotal = L_SEQ * EMB;
    int wTotal   = 3 * EMB * EMB;
    int woTotal  = EMB * EMB;

    // 1. input / weight splits (fp16 digits)
    split_hlh<<<(actTotal + 255) / 256, 256>>>(query, aq, actTotal);
    split_hlh<<<(actTotal + 255) / 256, 256>>>(key,   ak, actTotal);
    split_hlh<<<(actTotal + 255) / 256, 256>>>(value, av, actTotal);
    split_hhl<<<(wTotal  + 255) / 256, 256>>>(w_in,  wqkv, wTotal);
    split_hhl_perm<<<(woTotal + 255) / 256, 256>>>(w_out, wo, woTotal);

    // 2. QKV projection — fused split epilogues (permuted q/k, v fp32)
    dim3 qkv_grid(L_SEQ / 128, 12);
    gemm_qkv_kernel<<<qkv_grid, 256>>>(b_in);

    // 3. edge-type score LUT
    type_scores_kernel<<<(NHEAD * L_SEQ) / 8, 256>>>(embK);

    // 4. V transpose + split (permuted)
    dim3 vt_grid(L_SEQ / 64, NHEAD);
    v_split_transpose<<<vt_grid, 256>>>();

    // 5. flash attention (128-row i-tiles, single wave)
    cudaFuncSetAttribute(attn_mma_kernel, cudaFuncAttributeMaxDynamicSharedMemorySize,
                         ATTN_SMEM);
    dim3 attn_grid(L_SEQ / 128, NHEAD);
    attn_mma_kernel<<<attn_grid, 256, ATTN_SMEM>>>(eid);

    // 6. out projection
    dim3 out_grid(L_SEQ / 128, 4);
    gemm_out_kernel<<<out_grid, 256>>>(b_out, out);
}